// round 7
// baseline (speedup 1.0000x reference)
#include <cuda_runtime.h>
#include <math.h>

#define BB 2
#define SS 2048
#define DD 768
#define HH 12
#define DKK 64

__device__ float g_qp[BB * SS * DD];
__device__ float g_kp[BB * SS * DD];
__device__ float g_am[BB * HH * DKK];
__device__ float g_asc[BB * HH * SS];

__device__ __forceinline__ unsigned f2tf(float x) {
    unsigned u;
    asm("cvt.rna.tf32.f32 %0, %1;" : "=r"(u) : "f"(x));
    return u;
}

__device__ __forceinline__ void mma_tf32(float c[4], const unsigned a[4],
                                         unsigned b0, unsigned b1) {
    asm volatile(
        "mma.sync.aligned.m16n8k8.row.col.f32.tf32.tf32.f32 "
        "{%0,%1,%2,%3},{%4,%5,%6,%7},{%8,%9},{%0,%1,%2,%3};"
        : "+f"(c[0]), "+f"(c[1]), "+f"(c[2]), "+f"(c[3])
        : "r"(a[0]), "r"(a[1]), "r"(a[2]), "r"(a[3]), "r"(b0), "r"(b1));
}

// ---------- kernel 1: projections C[4096,768] = X @ W + b (z=0:q, z=1:k) ----------
__global__ __launch_bounds__(256) void proj_kernel(
    const float* __restrict__ qin, const float* __restrict__ Wq, const float* __restrict__ bq,
    const float* __restrict__ kin, const float* __restrict__ Wk, const float* __restrict__ bk)
{
    const float *X, *W, *bias; float* out;
    if (blockIdx.z == 0) { X = qin; W = Wq; bias = bq; out = g_qp; }
    else                 { X = kin; W = Wk; bias = bk; out = g_kp; }

    __shared__ unsigned As[128][36];
    __shared__ unsigned Bs[32][72];

    const int tid = threadIdx.x, lane = tid & 31, wid = tid >> 5;
    const int gid = lane >> 2, tig = lane & 3;
    const int wm = wid & 3, wn = wid >> 2;
    const int m0 = blockIdx.y * 128, n0 = blockIdx.x * 64;

    float acc[2][4][4];
#pragma unroll
    for (int i = 0; i < 2; i++)
#pragma unroll
        for (int j = 0; j < 4; j++)
#pragma unroll
            for (int k = 0; k < 4; k++) acc[i][j][k] = 0.f;

    const int arow = tid >> 3, acol = (tid & 7) * 4;
    const int brow = tid >> 4, bcol = (tid & 15) * 4;

    float4 ra[4], rb[2];
#pragma unroll
    for (int it = 0; it < 4; it++)
        ra[it] = *(const float4*)&X[(m0 + arow + it * 32) * DD + acol];
#pragma unroll
    for (int it = 0; it < 2; it++)
        rb[it] = *(const float4*)&W[(brow + it * 16) * DD + n0 + bcol];

    for (int kc = 0; kc < 24; kc++) {
#pragma unroll
        for (int it = 0; it < 4; it++) {
            uint4 v = { f2tf(ra[it].x), f2tf(ra[it].y), f2tf(ra[it].z), f2tf(ra[it].w) };
            *(uint4*)&As[arow + it * 32][acol] = v;
        }
#pragma unroll
        for (int it = 0; it < 2; it++) {
            uint4 v = { f2tf(rb[it].x), f2tf(rb[it].y), f2tf(rb[it].z), f2tf(rb[it].w) };
            *(uint4*)&Bs[brow + it * 16][bcol] = v;
        }
        __syncthreads();
        if (kc + 1 < 24) {
            const int k1 = (kc + 1) * 32;
#pragma unroll
            for (int it = 0; it < 4; it++)
                ra[it] = *(const float4*)&X[(m0 + arow + it * 32) * DD + k1 + acol];
#pragma unroll
            for (int it = 0; it < 2; it++)
                rb[it] = *(const float4*)&W[(k1 + brow + it * 16) * DD + n0 + bcol];
        }
#pragma unroll
        for (int kk = 0; kk < 4; kk++) {
            unsigned afr[2][4], bfr[4][2];
#pragma unroll
            for (int ms = 0; ms < 2; ms++) {
                const int r = wm * 32 + ms * 16 + gid;
                afr[ms][0] = As[r][kk * 8 + tig];
                afr[ms][1] = As[r + 8][kk * 8 + tig];
                afr[ms][2] = As[r][kk * 8 + tig + 4];
                afr[ms][3] = As[r + 8][kk * 8 + tig + 4];
            }
#pragma unroll
            for (int ns = 0; ns < 4; ns++) {
                const int cc = wn * 32 + ns * 8 + gid;
                bfr[ns][0] = Bs[kk * 8 + tig][cc];
                bfr[ns][1] = Bs[kk * 8 + tig + 4][cc];
            }
#pragma unroll
            for (int ms = 0; ms < 2; ms++)
#pragma unroll
                for (int ns = 0; ns < 4; ns++)
                    mma_tf32(acc[ms][ns], afr[ms], bfr[ns][0], bfr[ns][1]);
        }
        __syncthreads();
    }
#pragma unroll
    for (int ms = 0; ms < 2; ms++) {
        const int r = m0 + wm * 32 + ms * 16 + gid;
#pragma unroll
        for (int ns = 0; ns < 4; ns++) {
            const int c = n0 + wn * 32 + ns * 8 + 2 * tig;
            const float2 bb = *(const float2*)&bias[c];
            float2 v0 = { acc[ms][ns][0] + bb.x, acc[ms][ns][1] + bb.y };
            float2 v1 = { acc[ms][ns][2] + bb.x, acc[ms][ns][3] + bb.y };
            *(float2*)&out[r * DD + c]       = v0;
            *(float2*)&out[(r + 8) * DD + c] = v1;
        }
    }
}

// ---------- kernel 2: am[b,h,e] ----------
__global__ void am_kernel(const float* __restrict__ aspect, const float* __restrict__ Wd,
                          const float* __restrict__ bd, const float* __restrict__ Wm)
{
    __shared__ float a_s[BB][DKK];
    const int tid = threadIdx.x;
    if (tid < BB * DKK) {
        const int b = tid / DKK, d = tid % DKK;
        float s = bd[d];
        for (int k = 0; k < DD; k++) s += aspect[b * DD + k] * Wd[k * DKK + d];
        a_s[b][d] = s;
    }
    __syncthreads();
    for (int idx = tid; idx < BB * HH * DKK; idx += 256) {
        const int b = idx / (HH * DKK);
        const int rem = idx % (HH * DKK);
        const int h = rem / DKK, e = rem % DKK;
        float s = 0.f;
#pragma unroll
        for (int d = 0; d < DKK; d++) s += a_s[b][d] * Wm[(h * DKK + d) * DKK + e];
        g_am[idx] = s;
    }
}

// ---------- kernel 3: asc[b,h,t] = tanh(am . k_t + bias_m) ----------
__global__ __launch_bounds__(256) void asc_kernel(const float* __restrict__ bias_m)
{
    const int idx = blockIdx.x * 256 + threadIdx.x;
    const int t = idx % SS, bh = idx / SS;
    const int h = bh % HH, b = bh / HH;
    const float4* amp = (const float4*)&g_am[bh * DKK];
    const float4* kp  = (const float4*)&g_kp[(b * SS + t) * DD + h * DKK];
    float s = 0.f;
#pragma unroll
    for (int i = 0; i < 16; i++) {
        const float4 a = amp[i], k = kp[i];
        s += a.x * k.x + a.y * k.y + a.z * k.z + a.w * k.w;
    }
    g_asc[idx] = tanhf(s + bias_m[0]);
}

// ---------- kernel 4: fused scores + softmax ----------
#define ATT_SMEM_FLOATS 53456
__global__ __launch_bounds__(256) void attn_kernel(
    const int* __restrict__ mask, const float* __restrict__ short_t, float* __restrict__ out)
{
    extern __shared__ float sm[];
    unsigned* q_u  = (unsigned*)sm;            // 16 x 68
    unsigned* k_u  = (unsigned*)(sm + 1088);   // 2 x 128 x 68
    float* asc_sm  = sm + 18496;               // 2048
    float* p_sm    = sm + 20544;               // 16 x 2048
    float* part    = sm + 53312;               // 16 x 8
    float* inv     = sm + 53440;               // 16

    const int tid = threadIdx.x, lane = tid & 31, wid = tid >> 5;
    const int gid = lane >> 2, tig = lane & 3;
    const int h = blockIdx.y, b = blockIdx.z, s0 = blockIdx.x * 16;

    {   // q tile
        const int r = tid >> 4, c = (tid & 15) * 4;
        const float4 qv = *(const float4*)&g_qp[(b * SS + s0 + r) * DD + h * DKK + c];
        uint4 v = { f2tf(qv.x), f2tf(qv.y), f2tf(qv.z), f2tf(qv.w) };
        *(uint4*)&q_u[r * 68 + c] = v;
    }
    {   // asc row
        const float4* src = (const float4*)&g_asc[(b * HH + h) * SS];
        ((float4*)asc_sm)[tid]       = src[tid];
        ((float4*)asc_sm)[tid + 256] = src[tid + 256];
    }
    float4 kreg[8];
    const float* kbase = &g_kp[b * SS * DD + h * DKK];
#pragma unroll
    for (int it = 0; it < 8; it++) {
        const int f4 = tid + it * 256;
        kreg[it] = *(const float4*)&kbase[(f4 >> 4) * DD + (f4 & 15) * 4];
    }
#pragma unroll
    for (int it = 0; it < 8; it++) {
        const int f4 = tid + it * 256;
        uint4 v = { f2tf(kreg[it].x), f2tf(kreg[it].y), f2tf(kreg[it].z), f2tf(kreg[it].w) };
        *(uint4*)&k_u[(f4 >> 4) * 68 + (f4 & 15) * 4] = v;
    }
    __syncthreads();

    unsigned afr[8][4];
#pragma unroll
    for (int kk = 0; kk < 8; kk++) {
        afr[kk][0] = q_u[gid * 68 + kk * 8 + tig];
        afr[kk][1] = q_u[(gid + 8) * 68 + kk * 8 + tig];
        afr[kk][2] = q_u[gid * 68 + kk * 8 + tig + 4];
        afr[kk][3] = q_u[(gid + 8) * 68 + kk * 8 + tig + 4];
    }

    float sum0 = 0.f, sum1 = 0.f;
    const int r0g = s0 + gid;
    const int xr = (gid & 3) << 3;
    const long long sh_base = ((long long)(b * HH + h) * SS + r0g) * SS;
    const long long mk_base = ((long long)b * SS + r0g) * SS;

    for (int jt = 0; jt < 16; jt++) {
        const int cur = jt & 1;
        if (jt + 1 < 16) {
            const int t0n = (jt + 1) * 128;
#pragma unroll
            for (int it = 0; it < 8; it++) {
                const int f4 = tid + it * 256;
                kreg[it] = *(const float4*)&kbase[(t0n + (f4 >> 4)) * DD + (f4 & 15) * 4];
            }
        }
        unsigned* kb = k_u + cur * 8704;
        const int t0 = jt * 128;
#pragma unroll
        for (int ns = 0; ns < 2; ns++) {
            const int nb = wid * 16 + ns * 8;
            float acc[4] = {0.f, 0.f, 0.f, 0.f};
#pragma unroll
            for (int kk = 0; kk < 8; kk++) {
                const unsigned b0 = kb[(nb + gid) * 68 + kk * 8 + tig];
                const unsigned b1 = kb[(nb + gid) * 68 + kk * 8 + tig + 4];
                mma_tf32(acc, afr[kk], b0, b1);
            }
            const int c0 = t0 + nb + 2 * tig;
            const float a0 = asc_sm[c0], a1 = asc_sm[c0 + 1];
            const float2 sh0 = *(const float2*)&short_t[sh_base + c0];
            const float2 sh1 = *(const float2*)&short_t[sh_base + 8 * SS + c0];
            const int2 m0v = *(const int2*)&mask[mk_base + c0];
            const int2 m1v = *(const int2*)&mask[mk_base + 8 * SS + c0];

            float s00 = acc[0] * 0.125f + a0; if (m0v.x == 0) s00 = -1e9f; s00 += sh0.x;
            float s01 = acc[1] * 0.125f + a1; if (m0v.y == 0) s01 = -1e9f; s01 += sh0.y;
            float s10 = acc[2] * 0.125f + a0; if (m1v.x == 0) s10 = -1e9f; s10 += sh1.x;
            float s11 = acc[3] * 0.125f + a1; if (m1v.y == 0) s11 = -1e9f; s11 += sh1.y;

            const float p00 = __expf(s00), p01 = __expf(s01);
            const float p10 = __expf(s10), p11 = __expf(s11);
            const int cs = c0 ^ xr;
            *(float2*)&p_sm[gid * 2048 + cs]       = make_float2(p00, p01);
            *(float2*)&p_sm[(gid + 8) * 2048 + cs] = make_float2(p10, p11);
            sum0 += p00 + p01;
            sum1 += p10 + p11;
        }
        if (jt + 1 < 16) {
            unsigned* kn = k_u + (cur ^ 1) * 8704;
#pragma unroll
            for (int it = 0; it < 8; it++) {
                const int f4 = tid + it * 256;
                uint4 v = { f2tf(kreg[it].x), f2tf(kreg[it].y), f2tf(kreg[it].z), f2tf(kreg[it].w) };
                *(uint4*)&kn[(f4 >> 4) * 68 + (f4 & 15) * 4] = v;
            }
        }
        __syncthreads();
    }

    // row-sum reduction (deterministic): reduce over tig, then over warps via smem
    sum0 += __shfl_xor_sync(0xffffffff, sum0, 1);
    sum0 += __shfl_xor_sync(0xffffffff, sum0, 2);
    sum1 += __shfl_xor_sync(0xffffffff, sum1, 1);
    sum1 += __shfl_xor_sync(0xffffffff, sum1, 2);
    if (tig == 0) {
        part[gid * 8 + wid]       = sum0;
        part[(gid + 8) * 8 + wid] = sum1;
    }
    __syncthreads();
    if (tid < 16) {
        float t = 0.f;
#pragma unroll
        for (int w = 0; w < 8; w++) t += part[tid * 8 + w];
        inv[tid] = 1.0f / t;
    }
    __syncthreads();

    // normalized coalesced write
    const long long ob = ((long long)(b * HH + h) * SS + s0) * SS;
    for (int i = tid; i < 8192; i += 256) {
        const int row = i >> 9;
        const int c = (i & 511) * 4;
        const int xrr = (row & 3) << 3;
        float4 p = *(const float4*)&p_sm[row * 2048 + (c ^ xrr)];
        const float s = inv[row];
        p.x *= s; p.y *= s; p.z *= s; p.w *= s;
        *(float4*)&out[ob + (long long)row * SS + c] = p;
    }
}

extern "C" void kernel_launch(void* const* d_in, const int* in_sizes, int n_in,
                              void* d_out, int out_size) {
    const float* query  = (const float*)d_in[0];
    const float* key    = (const float*)d_in[1];
    const int*   mask   = (const int*)d_in[2];
    const float* short_t= (const float*)d_in[3];
    const float* aspect = (const float*)d_in[4];
    const float* Wq     = (const float*)d_in[5];
    const float* bq     = (const float*)d_in[6];
    const float* Wk     = (const float*)d_in[7];
    const float* bk     = (const float*)d_in[8];
    const float* Wd     = (const float*)d_in[9];
    const float* bd     = (const float*)d_in[10];
    const float* Wm     = (const float*)d_in[11];
    const float* bias_m = (const float*)d_in[12];
    float* out = (float*)d_out;

    static int smem_set = 0;
    if (!smem_set) {
        cudaFuncSetAttribute(attn_kernel, cudaFuncAttributeMaxDynamicSharedMemorySize,
                             ATT_SMEM_FLOATS * 4);
        smem_set = 1;
    }

    proj_kernel<<<dim3(12, 32, 2), 256>>>(query, Wq, bq, key, Wk, bk);
    am_kernel<<<1, 256>>>(aspect, Wd, bd, Wm);
    asc_kernel<<<BB * HH * SS / 256, 256>>>(bias_m);
    attn_kernel<<<dim3(SS / 16, HH, BB), 256, ATT_SMEM_FLOATS * 4>>>(mask, short_t, out);
}

// round 9
// speedup vs baseline: 1.3100x; 1.3100x over previous
#include <cuda_runtime.h>
#include <math.h>

#define BB 2
#define SS 2048
#define DD 768
#define HH 12
#define DKK 64

__device__ float g_qp[BB * SS * DD];
__device__ float g_kp[BB * SS * DD];
__device__ float g_am[BB * HH * DKK];
__device__ float g_asc[BB * HH * SS];

__device__ __forceinline__ unsigned f2tf(float x) {
    unsigned u;
    asm("cvt.rna.tf32.f32 %0, %1;" : "=r"(u) : "f"(x));
    return u;
}

__device__ __forceinline__ void mma_tf32(float c[4], const unsigned a[4],
                                         unsigned b0, unsigned b1) {
    asm volatile(
        "mma.sync.aligned.m16n8k8.row.col.f32.tf32.tf32.f32 "
        "{%0,%1,%2,%3},{%4,%5,%6,%7},{%8,%9},{%0,%1,%2,%3};"
        : "+f"(c[0]), "+f"(c[1]), "+f"(c[2]), "+f"(c[3])
        : "r"(a[0]), "r"(a[1]), "r"(a[2]), "r"(a[3]), "r"(b0), "r"(b1));
}

// ---------- kernel 1: projections C[4096,768] = X @ W + b (z=0:q, z=1:k) ----------
__global__ __launch_bounds__(256) void proj_kernel(
    const float* __restrict__ qin, const float* __restrict__ Wq, const float* __restrict__ bq,
    const float* __restrict__ kin, const float* __restrict__ Wk, const float* __restrict__ bk)
{
    const float *X, *W, *bias; float* out;
    if (blockIdx.z == 0) { X = qin; W = Wq; bias = bq; out = g_qp; }
    else                 { X = kin; W = Wk; bias = bk; out = g_kp; }

    __shared__ unsigned As[128][36];
    __shared__ unsigned Bs[32][72];

    const int tid = threadIdx.x, lane = tid & 31, wid = tid >> 5;
    const int gid = lane >> 2, tig = lane & 3;
    const int wm = wid & 3, wn = wid >> 2;
    const int m0 = blockIdx.y * 128, n0 = blockIdx.x * 64;

    float acc[2][4][4];
#pragma unroll
    for (int i = 0; i < 2; i++)
#pragma unroll
        for (int j = 0; j < 4; j++)
#pragma unroll
            for (int k = 0; k < 4; k++) acc[i][j][k] = 0.f;

    const int arow = tid >> 3, acol = (tid & 7) * 4;
    const int brow = tid >> 4, bcol = (tid & 15) * 4;

    float4 ra[4], rb[2];
#pragma unroll
    for (int it = 0; it < 4; it++)
        ra[it] = *(const float4*)&X[(m0 + arow + it * 32) * DD + acol];
#pragma unroll
    for (int it = 0; it < 2; it++)
        rb[it] = *(const float4*)&W[(brow + it * 16) * DD + n0 + bcol];

    for (int kc = 0; kc < 24; kc++) {
#pragma unroll
        for (int it = 0; it < 4; it++) {
            uint4 v = { f2tf(ra[it].x), f2tf(ra[it].y), f2tf(ra[it].z), f2tf(ra[it].w) };
            *(uint4*)&As[arow + it * 32][acol] = v;
        }
#pragma unroll
        for (int it = 0; it < 2; it++) {
            uint4 v = { f2tf(rb[it].x), f2tf(rb[it].y), f2tf(rb[it].z), f2tf(rb[it].w) };
            *(uint4*)&Bs[brow + it * 16][bcol] = v;
        }
        __syncthreads();
        if (kc + 1 < 24) {
            const int k1 = (kc + 1) * 32;
#pragma unroll
            for (int it = 0; it < 4; it++)
                ra[it] = *(const float4*)&X[(m0 + arow + it * 32) * DD + k1 + acol];
#pragma unroll
            for (int it = 0; it < 2; it++)
                rb[it] = *(const float4*)&W[(k1 + brow + it * 16) * DD + n0 + bcol];
        }
#pragma unroll
        for (int kk = 0; kk < 4; kk++) {
            unsigned afr[2][4], bfr[4][2];
#pragma unroll
            for (int ms = 0; ms < 2; ms++) {
                const int r = wm * 32 + ms * 16 + gid;
                afr[ms][0] = As[r][kk * 8 + tig];
                afr[ms][1] = As[r + 8][kk * 8 + tig];
                afr[ms][2] = As[r][kk * 8 + tig + 4];
                afr[ms][3] = As[r + 8][kk * 8 + tig + 4];
            }
#pragma unroll
            for (int ns = 0; ns < 4; ns++) {
                const int cc = wn * 32 + ns * 8 + gid;
                bfr[ns][0] = Bs[kk * 8 + tig][cc];
                bfr[ns][1] = Bs[kk * 8 + tig + 4][cc];
            }
#pragma unroll
            for (int ms = 0; ms < 2; ms++)
#pragma unroll
                for (int ns = 0; ns < 4; ns++)
                    mma_tf32(acc[ms][ns], afr[ms], bfr[ns][0], bfr[ns][1]);
        }
        __syncthreads();
    }
#pragma unroll
    for (int ms = 0; ms < 2; ms++) {
        const int r = m0 + wm * 32 + ms * 16 + gid;
#pragma unroll
        for (int ns = 0; ns < 4; ns++) {
            const int c = n0 + wn * 32 + ns * 8 + 2 * tig;
            const float2 bb = *(const float2*)&bias[c];
            float2 v0 = { acc[ms][ns][0] + bb.x, acc[ms][ns][1] + bb.y };
            float2 v1 = { acc[ms][ns][2] + bb.x, acc[ms][ns][3] + bb.y };
            *(float2*)&out[r * DD + c]       = v0;
            *(float2*)&out[(r + 8) * DD + c] = v1;
        }
    }
}

// ---------- kernel 2: am[b,h,e] ----------
__global__ void am_kernel(const float* __restrict__ aspect, const float* __restrict__ Wd,
                          const float* __restrict__ bd, const float* __restrict__ Wm)
{
    __shared__ float a_s[BB][DKK];
    const int tid = threadIdx.x;
    if (tid < BB * DKK) {
        const int b = tid / DKK, d = tid % DKK;
        float s = bd[d];
        for (int k = 0; k < DD; k++) s += aspect[b * DD + k] * Wd[k * DKK + d];
        a_s[b][d] = s;
    }
    __syncthreads();
    for (int idx = tid; idx < BB * HH * DKK; idx += 256) {
        const int b = idx / (HH * DKK);
        const int rem = idx % (HH * DKK);
        const int h = rem / DKK, e = rem % DKK;
        float s = 0.f;
#pragma unroll
        for (int d = 0; d < DKK; d++) s += a_s[b][d] * Wm[(h * DKK + d) * DKK + e];
        g_am[idx] = s;
    }
}

// ---------- kernel 3: asc[b,h,t] = tanh(am . k_t + bias_m) ----------
__global__ __launch_bounds__(256) void asc_kernel(const float* __restrict__ bias_m)
{
    const int idx = blockIdx.x * 256 + threadIdx.x;
    const int t = idx % SS, bh = idx / SS;
    const int h = bh % HH, b = bh / HH;
    const float4* amp = (const float4*)&g_am[bh * DKK];
    const float4* kp  = (const float4*)&g_kp[(b * SS + t) * DD + h * DKK];
    float s = 0.f;
#pragma unroll
    for (int i = 0; i < 16; i++) {
        const float4 a = amp[i], k = kp[i];
        s += a.x * k.x + a.y * k.y + a.z * k.z + a.w * k.w;
    }
    g_asc[idx] = tanhf(s + bias_m[0]);
}

// ---------- kernel 4: fused scores + softmax, in-CTA recompute 2-pass ----------
// smem floats: q_u 1088 | k_u 17408 (2 x 128x68) | asc 2048 | part 128 | inv 16
#define ATT_SMEM_FLOATS 20688
__global__ __launch_bounds__(256, 2) void attn_kernel(
    const int* __restrict__ mask, const float* __restrict__ short_t, float* __restrict__ out)
{
    extern __shared__ float sm[];
    unsigned* q_u  = (unsigned*)sm;            // 16 x 68
    unsigned* k_u  = (unsigned*)(sm + 1088);   // 2 x 128 x 68
    float* asc_sm  = sm + 18496;               // 2048
    float* part    = sm + 20544;               // 16 x 8
    float* inv     = sm + 20672;               // 16

    const int tid = threadIdx.x, lane = tid & 31, wid = tid >> 5;
    const int gid = lane >> 2, tig = lane & 3;
    const int h = blockIdx.y, b = blockIdx.z, s0 = blockIdx.x * 16;

    {   // q tile
        const int r = tid >> 4, c = (tid & 15) * 4;
        const float4 qv = *(const float4*)&g_qp[(b * SS + s0 + r) * DD + h * DKK + c];
        uint4 v = { f2tf(qv.x), f2tf(qv.y), f2tf(qv.z), f2tf(qv.w) };
        *(uint4*)&q_u[r * 68 + c] = v;
    }
    {   // asc row
        const float4* src = (const float4*)&g_asc[(b * HH + h) * SS];
        ((float4*)asc_sm)[tid]       = src[tid];
        ((float4*)asc_sm)[tid + 256] = src[tid + 256];
    }
    float4 kreg[8];
    const float* kbase = &g_kp[b * SS * DD + h * DKK];
#pragma unroll
    for (int it = 0; it < 8; it++) {
        const int f4 = tid + it * 256;
        kreg[it] = *(const float4*)&kbase[(f4 >> 4) * DD + (f4 & 15) * 4];
    }
#pragma unroll
    for (int it = 0; it < 8; it++) {
        const int f4 = tid + it * 256;
        uint4 v = { f2tf(kreg[it].x), f2tf(kreg[it].y), f2tf(kreg[it].z), f2tf(kreg[it].w) };
        *(uint4*)&k_u[(f4 >> 4) * 68 + (f4 & 15) * 4] = v;
    }
    __syncthreads();

    unsigned afr[8][4];
#pragma unroll
    for (int kk = 0; kk < 8; kk++) {
        afr[kk][0] = q_u[gid * 68 + kk * 8 + tig];
        afr[kk][1] = q_u[(gid + 8) * 68 + kk * 8 + tig];
        afr[kk][2] = q_u[gid * 68 + kk * 8 + tig + 4];
        afr[kk][3] = q_u[(gid + 8) * 68 + kk * 8 + tig + 4];
    }

    float sum0 = 0.f, sum1 = 0.f;
    float inv0 = 0.f, inv1 = 0.f;
    const int r0g = s0 + gid;
    const long long sh_base = ((long long)(b * HH + h) * SS + r0g) * SS;
    const long long mk_base = ((long long)b * SS + r0g) * SS;
    const long long ob      = sh_base;   // same indexing as short

    // 32 iterations: it 0..15 = sum pass, it 16..31 = write pass (recompute)
    for (int it = 0; it < 32; it++) {
        const int jt  = it & 15;
        const int cur = it & 1;
        if (it < 31) {   // prefetch next k tile (wraps at it=15 back to tile 0)
            const int t0n = ((it + 1) & 15) * 128;
#pragma unroll
            for (int i = 0; i < 8; i++) {
                const int f4 = tid + i * 256;
                kreg[i] = *(const float4*)&kbase[(t0n + (f4 >> 4)) * DD + (f4 & 15) * 4];
            }
        }
        unsigned* kb = k_u + cur * 8704;
        const int t0 = jt * 128;
        const bool wr = (it >= 16);
#pragma unroll
        for (int ns = 0; ns < 2; ns++) {
            const int nb = wid * 16 + ns * 8;
            float acc[4] = {0.f, 0.f, 0.f, 0.f};
#pragma unroll
            for (int kk = 0; kk < 8; kk++) {
                const unsigned b0 = kb[(nb + gid) * 68 + kk * 8 + tig];
                const unsigned b1 = kb[(nb + gid) * 68 + kk * 8 + tig + 4];
                mma_tf32(acc, afr[kk], b0, b1);
            }
            const int c0 = t0 + nb + 2 * tig;
            const float a0 = asc_sm[c0], a1 = asc_sm[c0 + 1];
            const float2 sh0 = *(const float2*)&short_t[sh_base + c0];
            const float2 sh1 = *(const float2*)&short_t[sh_base + 8 * SS + c0];
            const int2 m0v = *(const int2*)&mask[mk_base + c0];
            const int2 m1v = *(const int2*)&mask[mk_base + 8 * SS + c0];

            float s00 = acc[0] * 0.125f + a0; if (m0v.x == 0) s00 = -1e9f; s00 += sh0.x;
            float s01 = acc[1] * 0.125f + a1; if (m0v.y == 0) s01 = -1e9f; s01 += sh0.y;
            float s10 = acc[2] * 0.125f + a0; if (m1v.x == 0) s10 = -1e9f; s10 += sh1.x;
            float s11 = acc[3] * 0.125f + a1; if (m1v.y == 0) s11 = -1e9f; s11 += sh1.y;

            const float p00 = __expf(s00), p01 = __expf(s01);
            const float p10 = __expf(s10), p11 = __expf(s11);

            if (!wr) {
                sum0 += p00 + p01;
                sum1 += p10 + p11;
            } else {
                *(float2*)&out[ob + c0]          = make_float2(p00 * inv0, p01 * inv0);
                *(float2*)&out[ob + 8 * SS + c0] = make_float2(p10 * inv1, p11 * inv1);
            }
        }
        if (it == 15) {   // row sums -> inv (deterministic reduction)
            sum0 += __shfl_xor_sync(0xffffffff, sum0, 1);
            sum0 += __shfl_xor_sync(0xffffffff, sum0, 2);
            sum1 += __shfl_xor_sync(0xffffffff, sum1, 1);
            sum1 += __shfl_xor_sync(0xffffffff, sum1, 2);
            if (tig == 0) {
                part[gid * 8 + wid]       = sum0;
                part[(gid + 8) * 8 + wid] = sum1;
            }
            __syncthreads();
            if (tid < 16) {
                float t = 0.f;
#pragma unroll
                for (int w = 0; w < 8; w++) t += part[tid * 8 + w];
                inv[tid] = 1.0f / t;
            }
            __syncthreads();
            inv0 = inv[gid];
            inv1 = inv[gid + 8];
        }
        if (it < 31) {   // commit prefetched k tile to the other buffer
            unsigned* kn = k_u + (cur ^ 1) * 8704;
#pragma unroll
            for (int i = 0; i < 8; i++) {
                const int f4 = tid + i * 256;
                uint4 v = { f2tf(kreg[i].x), f2tf(kreg[i].y), f2tf(kreg[i].z), f2tf(kreg[i].w) };
                *(uint4*)&kn[(f4 >> 4) * 68 + (f4 & 15) * 4] = v;
            }
        }
        __syncthreads();
    }
}

extern "C" void kernel_launch(void* const* d_in, const int* in_sizes, int n_in,
                              void* d_out, int out_size) {
    const float* query  = (const float*)d_in[0];
    const float* key    = (const float*)d_in[1];
    const int*   mask   = (const int*)d_in[2];
    const float* short_t= (const float*)d_in[3];
    const float* aspect = (const float*)d_in[4];
    const float* Wq     = (const float*)d_in[5];
    const float* bq     = (const float*)d_in[6];
    const float* Wk     = (const float*)d_in[7];
    const float* bk     = (const float*)d_in[8];
    const float* Wd     = (const float*)d_in[9];
    const float* bd     = (const float*)d_in[10];
    const float* Wm     = (const float*)d_in[11];
    const float* bias_m = (const float*)d_in[12];
    float* out = (float*)d_out;

    static int smem_set = 0;
    if (!smem_set) {
        cudaFuncSetAttribute(attn_kernel, cudaFuncAttributeMaxDynamicSharedMemorySize,
                             ATT_SMEM_FLOATS * 4);
        smem_set = 1;
    }

    proj_kernel<<<dim3(12, 32, 2), 256>>>(query, Wq, bq, key, Wk, bk);
    am_kernel<<<1, 256>>>(aspect, Wd, bd, Wm);
    asc_kernel<<<BB * HH * SS / 256, 256>>>(bias_m);
    attn_kernel<<<dim3(SS / 16, HH, BB), 256, ATT_SMEM_FLOATS * 4>>>(mask, short_t, out);
}

// round 10
// speedup vs baseline: 1.4791x; 1.1291x over previous
#include <cuda_runtime.h>
#include <math.h>

#define BB 2
#define SS 2048
#define DD 768
#define HH 12
#define DKK 64

__device__ float g_qp[BB * SS * DD];
__device__ float g_kp[BB * SS * DD];   // NOTE: holds tf32-ROUNDED k values
__device__ float g_am[BB * HH * DKK];
__device__ float g_asc[BB * HH * SS];

__device__ __forceinline__ unsigned f2tf(float x) {
    unsigned u;
    asm("cvt.rna.tf32.f32 %0, %1;" : "=r"(u) : "f"(x));
    return u;
}

__device__ __forceinline__ void mma_tf32(float c[4], const unsigned a[4],
                                         unsigned b0, unsigned b1) {
    asm volatile(
        "mma.sync.aligned.m16n8k8.row.col.f32.tf32.tf32.f32 "
        "{%0,%1,%2,%3},{%4,%5,%6,%7},{%8,%9},{%0,%1,%2,%3};"
        : "+f"(c[0]), "+f"(c[1]), "+f"(c[2]), "+f"(c[3])
        : "r"(a[0]), "r"(a[1]), "r"(a[2]), "r"(a[3]), "r"(b0), "r"(b1));
}

__device__ __forceinline__ void cp_async16(float* smem_dst, const float* gsrc) {
    unsigned saddr = (unsigned)__cvta_generic_to_shared(smem_dst);
    asm volatile("cp.async.cg.shared.global [%0], [%1], 16;" :: "r"(saddr), "l"(gsrc));
}
#define CP_COMMIT() asm volatile("cp.async.commit_group;")
#define CP_WAIT0()  asm volatile("cp.async.wait_group 0;")

// ---------- kernel 1: projections C[4096,768] = X @ W + b (z=0:q, z=1:k) ----------
// z=1 (k) output is rounded to tf32 before store so attn can cp.async raw bits.
__global__ __launch_bounds__(256) void proj_kernel(
    const float* __restrict__ qin, const float* __restrict__ Wq, const float* __restrict__ bq,
    const float* __restrict__ kin, const float* __restrict__ Wk, const float* __restrict__ bk)
{
    const float *X, *W, *bias; float* out;
    const bool round_out = (blockIdx.z == 1);
    if (!round_out) { X = qin; W = Wq; bias = bq; out = g_qp; }
    else            { X = kin; W = Wk; bias = bk; out = g_kp; }

    __shared__ unsigned As[128][36];
    __shared__ unsigned Bs[32][72];

    const int tid = threadIdx.x, lane = tid & 31, wid = tid >> 5;
    const int gid = lane >> 2, tig = lane & 3;
    const int wm = wid & 3, wn = wid >> 2;
    const int m0 = blockIdx.y * 128, n0 = blockIdx.x * 64;

    float acc[2][4][4];
#pragma unroll
    for (int i = 0; i < 2; i++)
#pragma unroll
        for (int j = 0; j < 4; j++)
#pragma unroll
            for (int k = 0; k < 4; k++) acc[i][j][k] = 0.f;

    const int arow = tid >> 3, acol = (tid & 7) * 4;
    const int brow = tid >> 4, bcol = (tid & 15) * 4;

    float4 ra[4], rb[2];
#pragma unroll
    for (int it = 0; it < 4; it++)
        ra[it] = *(const float4*)&X[(m0 + arow + it * 32) * DD + acol];
#pragma unroll
    for (int it = 0; it < 2; it++)
        rb[it] = *(const float4*)&W[(brow + it * 16) * DD + n0 + bcol];

    for (int kc = 0; kc < 24; kc++) {
#pragma unroll
        for (int it = 0; it < 4; it++) {
            uint4 v = { f2tf(ra[it].x), f2tf(ra[it].y), f2tf(ra[it].z), f2tf(ra[it].w) };
            *(uint4*)&As[arow + it * 32][acol] = v;
        }
#pragma unroll
        for (int it = 0; it < 2; it++) {
            uint4 v = { f2tf(rb[it].x), f2tf(rb[it].y), f2tf(rb[it].z), f2tf(rb[it].w) };
            *(uint4*)&Bs[brow + it * 16][bcol] = v;
        }
        __syncthreads();
        if (kc + 1 < 24) {
            const int k1 = (kc + 1) * 32;
#pragma unroll
            for (int it = 0; it < 4; it++)
                ra[it] = *(const float4*)&X[(m0 + arow + it * 32) * DD + k1 + acol];
#pragma unroll
            for (int it = 0; it < 2; it++)
                rb[it] = *(const float4*)&W[(k1 + brow + it * 16) * DD + n0 + bcol];
        }
#pragma unroll
        for (int kk = 0; kk < 4; kk++) {
            unsigned afr[2][4], bfr[4][2];
#pragma unroll
            for (int ms = 0; ms < 2; ms++) {
                const int r = wm * 32 + ms * 16 + gid;
                afr[ms][0] = As[r][kk * 8 + tig];
                afr[ms][1] = As[r + 8][kk * 8 + tig];
                afr[ms][2] = As[r][kk * 8 + tig + 4];
                afr[ms][3] = As[r + 8][kk * 8 + tig + 4];
            }
#pragma unroll
            for (int ns = 0; ns < 4; ns++) {
                const int cc = wn * 32 + ns * 8 + gid;
                bfr[ns][0] = Bs[kk * 8 + tig][cc];
                bfr[ns][1] = Bs[kk * 8 + tig + 4][cc];
            }
#pragma unroll
            for (int ms = 0; ms < 2; ms++)
#pragma unroll
                for (int ns = 0; ns < 4; ns++)
                    mma_tf32(acc[ms][ns], afr[ms], bfr[ns][0], bfr[ns][1]);
        }
        __syncthreads();
    }
#pragma unroll
    for (int ms = 0; ms < 2; ms++) {
        const int r = m0 + wm * 32 + ms * 16 + gid;
#pragma unroll
        for (int ns = 0; ns < 4; ns++) {
            const int c = n0 + wn * 32 + ns * 8 + 2 * tig;
            const float2 bb = *(const float2*)&bias[c];
            float2 v0 = { acc[ms][ns][0] + bb.x, acc[ms][ns][1] + bb.y };
            float2 v1 = { acc[ms][ns][2] + bb.x, acc[ms][ns][3] + bb.y };
            if (round_out) {
                v0.x = __uint_as_float(f2tf(v0.x)); v0.y = __uint_as_float(f2tf(v0.y));
                v1.x = __uint_as_float(f2tf(v1.x)); v1.y = __uint_as_float(f2tf(v1.y));
            }
            *(float2*)&out[r * DD + c]       = v0;
            *(float2*)&out[(r + 8) * DD + c] = v1;
        }
    }
}

// ---------- kernel 2: am[b,h,e] ----------
__global__ void am_kernel(const float* __restrict__ aspect, const float* __restrict__ Wd,
                          const float* __restrict__ bd, const float* __restrict__ Wm)
{
    __shared__ float a_s[BB][DKK];
    const int tid = threadIdx.x;
    if (tid < BB * DKK) {
        const int b = tid / DKK, d = tid % DKK;
        float s = bd[d];
        for (int k = 0; k < DD; k++) s += aspect[b * DD + k] * Wd[k * DKK + d];
        a_s[b][d] = s;
    }
    __syncthreads();
    for (int idx = tid; idx < BB * HH * DKK; idx += 256) {
        const int b = idx / (HH * DKK);
        const int rem = idx % (HH * DKK);
        const int h = rem / DKK, e = rem % DKK;
        float s = 0.f;
#pragma unroll
        for (int d = 0; d < DKK; d++) s += a_s[b][d] * Wm[(h * DKK + d) * DKK + e];
        g_am[idx] = s;
    }
}

// ---------- kernel 3: asc[b,h,t] = tanh(am . k_t + bias_m) ----------
__global__ __launch_bounds__(256) void asc_kernel(const float* __restrict__ bias_m)
{
    const int idx = blockIdx.x * 256 + threadIdx.x;
    const int t = idx % SS, bh = idx / SS;
    const int h = bh % HH, b = bh / HH;
    const float4* amp = (const float4*)&g_am[bh * DKK];
    const float4* kp  = (const float4*)&g_kp[(b * SS + t) * DD + h * DKK];
    float s = 0.f;
#pragma unroll
    for (int i = 0; i < 16; i++) {
        const float4 a = amp[i], k = kp[i];
        s += a.x * k.x + a.y * k.y + a.z * k.z + a.w * k.w;
    }
    g_asc[idx] = tanhf(s + bias_m[0]);
}

// ---------- kernel 4: fused scores + softmax, M=32/CTA, cp.async k, 2-pass recompute ----------
// smem floats: q_u 2176 (32x68) | k 17408 (2 x 128x68) | asc 2048 | part 256 | inv 32
#define ATT_SMEM_FLOATS 21920
__global__ __launch_bounds__(256, 2) void attn_kernel(
    const int* __restrict__ mask, const float* __restrict__ short_t, float* __restrict__ out)
{
    extern __shared__ float sm[];
    unsigned* q_u = (unsigned*)sm;           // 32 x 68
    float* k_f    = sm + 2176;               // 2 x 128 x 68 (raw tf32-rounded fp32 bits)
    float* asc_sm = sm + 19584;              // 2048
    float* part   = sm + 21632;              // 32 x 8
    float* inv    = sm + 21888;              // 32

    const int tid = threadIdx.x, lane = tid & 31, wid = tid >> 5;
    const int gid = lane >> 2, tig = lane & 3;
    const int h = blockIdx.y, b = blockIdx.z, s0 = blockIdx.x * 32;

    const float* kbase = &g_kp[b * SS * DD + h * DKK];

    // prologue: cp.async k tile 0 into buffer 0
#pragma unroll
    for (int i = 0; i < 8; i++) {
        const int f4 = tid + i * 256;
        const int row = f4 >> 4, c4 = (f4 & 15) * 4;
        cp_async16(&k_f[row * 68 + c4], &kbase[row * DD + c4]);
    }
    CP_COMMIT();

    // q tile (32 rows) -> smem, rounded to tf32
#pragma unroll
    for (int i = 0; i < 2; i++) {
        const int idx = tid + i * 256;
        const int r = idx >> 4, c = (idx & 15) * 4;
        const float4 qv = *(const float4*)&g_qp[(b * SS + s0 + r) * DD + h * DKK + c];
        uint4 v = { f2tf(qv.x), f2tf(qv.y), f2tf(qv.z), f2tf(qv.w) };
        *(uint4*)&q_u[r * 68 + c] = v;
    }
    // asc row -> smem
    {
        const float4* src = (const float4*)&g_asc[(b * HH + h) * SS];
        ((float4*)asc_sm)[tid]       = src[tid];
        ((float4*)asc_sm)[tid + 256] = src[tid + 256];
    }
    CP_WAIT0();
    __syncthreads();

    // A fragments: 2 m16 tiles (rows s0..s0+15, s0+16..s0+31)
    unsigned afr[2][8][4];
#pragma unroll
    for (int mf = 0; mf < 2; mf++)
#pragma unroll
        for (int kk = 0; kk < 8; kk++) {
            const int r = mf * 16 + gid;
            afr[mf][kk][0] = q_u[r * 68 + kk * 8 + tig];
            afr[mf][kk][1] = q_u[(r + 8) * 68 + kk * 8 + tig];
            afr[mf][kk][2] = q_u[r * 68 + kk * 8 + tig + 4];
            afr[mf][kk][3] = q_u[(r + 8) * 68 + kk * 8 + tig + 4];
        }

    float sums[4] = {0.f, 0.f, 0.f, 0.f};
    float invr[4] = {0.f, 0.f, 0.f, 0.f};
    const int shb = ((b * HH + h) * SS + s0 + gid) * SS;   // fits int (<2^27)
    const int mkb = (b * SS + s0 + gid) * SS;

    // 32 iterations: it 0..15 sum pass, 16..31 write pass (recompute)
    for (int it = 0; it < 32; it++) {
        const int jt = it & 15, t0 = jt * 128;
        if (it < 31) {
            const int tn = ((it + 1) & 15) * 128;
            float* kd = k_f + ((it + 1) & 1) * 8704;
#pragma unroll
            for (int i = 0; i < 8; i++) {
                const int f4 = tid + i * 256;
                const int row = f4 >> 4, c4 = (f4 & 15) * 4;
                cp_async16(&kd[row * 68 + c4], &kbase[(tn + row) * DD + c4]);
            }
            CP_COMMIT();
        }
        const unsigned* kb = (const unsigned*)(k_f + (it & 1) * 8704);
        const bool wr = (it >= 16);
#pragma unroll
        for (int ns = 0; ns < 2; ns++) {
            const int nb = wid * 16 + ns * 8;
            float a0c[4] = {0.f, 0.f, 0.f, 0.f};
            float a1c[4] = {0.f, 0.f, 0.f, 0.f};
            const unsigned* kr = kb + (nb + gid) * 68 + tig;
#pragma unroll
            for (int kk = 0; kk < 8; kk++) {
                const unsigned b0 = kr[kk * 8];
                const unsigned b1 = kr[kk * 8 + 4];
                mma_tf32(a0c, afr[0][kk], b0, b1);
                mma_tf32(a1c, afr[1][kk], b0, b1);
            }
            const int c0 = t0 + nb + 2 * tig;
            const float2 av = *(const float2*)&asc_sm[c0];
#pragma unroll
            for (int rr = 0; rr < 4; rr++) {
                const float x0 = (rr < 2) ? a0c[(rr & 1) * 2]     : a1c[(rr & 1) * 2];
                const float x1 = (rr < 2) ? a0c[(rr & 1) * 2 + 1] : a1c[(rr & 1) * 2 + 1];
                const int off = rr * 8 * SS + c0;
                const float2 sh = *(const float2*)&short_t[shb + off];
                const int2  mv = *(const int2*)&mask[mkb + off];
                float sA = x0 * 0.125f + av.x; if (mv.x == 0) sA = -1e9f; sA += sh.x;
                float sB = x1 * 0.125f + av.y; if (mv.y == 0) sB = -1e9f; sB += sh.y;
                const float pA = __expf(sA), pB = __expf(sB);
                if (!wr) {
                    sums[rr] += pA + pB;
                } else {
                    *(float2*)&out[shb + off] = make_float2(pA * invr[rr], pB * invr[rr]);
                }
            }
        }
        if (it == 15) {   // deterministic row-sum reduction -> inv
#pragma unroll
            for (int rr = 0; rr < 4; rr++) {
                float s = sums[rr];
                s += __shfl_xor_sync(0xffffffff, s, 1);
                s += __shfl_xor_sync(0xffffffff, s, 2);
                if (tig == 0) part[(rr * 8 + gid) * 8 + wid] = s;
            }
            __syncthreads();
            if (tid < 32) {
                float t = 0.f;
#pragma unroll
                for (int w = 0; w < 8; w++) t += part[tid * 8 + w];
                inv[tid] = 1.0f / t;
            }
            __syncthreads();
            invr[0] = inv[gid];
            invr[1] = inv[gid + 8];
            invr[2] = inv[gid + 16];
            invr[3] = inv[gid + 24];
        }
        if (it < 31) CP_WAIT0();
        __syncthreads();
    }
}

extern "C" void kernel_launch(void* const* d_in, const int* in_sizes, int n_in,
                              void* d_out, int out_size) {
    const float* query  = (const float*)d_in[0];
    const float* key    = (const float*)d_in[1];
    const int*   mask   = (const int*)d_in[2];
    const float* short_t= (const float*)d_in[3];
    const float* aspect = (const float*)d_in[4];
    const float* Wq     = (const float*)d_in[5];
    const float* bq     = (const float*)d_in[6];
    const float* Wk     = (const float*)d_in[7];
    const float* bk     = (const float*)d_in[8];
    const float* Wd     = (const float*)d_in[9];
    const float* bd     = (const float*)d_in[10];
    const float* Wm     = (const float*)d_in[11];
    const float* bias_m = (const float*)d_in[12];
    float* out = (float*)d_out;

    static int smem_set = 0;
    if (!smem_set) {
        cudaFuncSetAttribute(attn_kernel, cudaFuncAttributeMaxDynamicSharedMemorySize,
                             ATT_SMEM_FLOATS * 4);
        smem_set = 1;
    }

    proj_kernel<<<dim3(12, 32, 2), 256>>>(query, Wq, bq, key, Wk, bk);
    am_kernel<<<1, 256>>>(aspect, Wd, bd, Wm);
    asc_kernel<<<BB * HH * SS / 256, 256>>>(bias_m);
    attn_kernel<<<dim3(SS / 32, HH, BB), 256, ATT_SMEM_FLOATS * 4>>>(mask, short_t, out);
}

// round 11
// speedup vs baseline: 1.6709x; 1.1296x over previous
#include <cuda_runtime.h>
#include <math.h>

#define BB 2
#define SS 2048
#define DD 768
#define HH 12
#define DKK 64

__device__ float g_qp[BB * SS * DD];
__device__ float g_kp[BB * SS * DD];   // NOTE: holds tf32-ROUNDED k values
__device__ float g_am[BB * HH * DKK];
__device__ float g_asc[BB * HH * SS];

__device__ __forceinline__ unsigned f2tf(float x) {
    unsigned u;
    asm("cvt.rna.tf32.f32 %0, %1;" : "=r"(u) : "f"(x));
    return u;
}

__device__ __forceinline__ void mma_tf32(float c[4], const unsigned a[4],
                                         unsigned b0, unsigned b1) {
    asm volatile(
        "mma.sync.aligned.m16n8k8.row.col.f32.tf32.tf32.f32 "
        "{%0,%1,%2,%3},{%4,%5,%6,%7},{%8,%9},{%0,%1,%2,%3};"
        : "+f"(c[0]), "+f"(c[1]), "+f"(c[2]), "+f"(c[3])
        : "r"(a[0]), "r"(a[1]), "r"(a[2]), "r"(a[3]), "r"(b0), "r"(b1));
}

__device__ __forceinline__ void cp_async16(float* smem_dst, const float* gsrc) {
    unsigned saddr = (unsigned)__cvta_generic_to_shared(smem_dst);
    asm volatile("cp.async.cg.shared.global [%0], [%1], 16;" :: "r"(saddr), "l"(gsrc));
}
#define CP_COMMIT() asm volatile("cp.async.commit_group;")
#define CP_WAIT0()  asm volatile("cp.async.wait_group 0;")

// ---------- kernel 1: projections C[4096,768] = X @ W + b (z=0:q, z=1:k) ----------
__global__ __launch_bounds__(256) void proj_kernel(
    const float* __restrict__ qin, const float* __restrict__ Wq, const float* __restrict__ bq,
    const float* __restrict__ kin, const float* __restrict__ Wk, const float* __restrict__ bk)
{
    const float *X, *W, *bias; float* out;
    const bool round_out = (blockIdx.z == 1);
    if (!round_out) { X = qin; W = Wq; bias = bq; out = g_qp; }
    else            { X = kin; W = Wk; bias = bk; out = g_kp; }

    __shared__ unsigned As[128][36];
    __shared__ unsigned Bs[32][72];

    const int tid = threadIdx.x, lane = tid & 31, wid = tid >> 5;
    const int gid = lane >> 2, tig = lane & 3;
    const int wm = wid & 3, wn = wid >> 2;
    const int m0 = blockIdx.y * 128, n0 = blockIdx.x * 64;

    float acc[2][4][4];
#pragma unroll
    for (int i = 0; i < 2; i++)
#pragma unroll
        for (int j = 0; j < 4; j++)
#pragma unroll
            for (int k = 0; k < 4; k++) acc[i][j][k] = 0.f;

    const int arow = tid >> 3, acol = (tid & 7) * 4;
    const int brow = tid >> 4, bcol = (tid & 15) * 4;

    float4 ra[4], rb[2];
#pragma unroll
    for (int it = 0; it < 4; it++)
        ra[it] = *(const float4*)&X[(m0 + arow + it * 32) * DD + acol];
#pragma unroll
    for (int it = 0; it < 2; it++)
        rb[it] = *(const float4*)&W[(brow + it * 16) * DD + n0 + bcol];

    for (int kc = 0; kc < 24; kc++) {
#pragma unroll
        for (int it = 0; it < 4; it++) {
            uint4 v = { f2tf(ra[it].x), f2tf(ra[it].y), f2tf(ra[it].z), f2tf(ra[it].w) };
            *(uint4*)&As[arow + it * 32][acol] = v;
        }
#pragma unroll
        for (int it = 0; it < 2; it++) {
            uint4 v = { f2tf(rb[it].x), f2tf(rb[it].y), f2tf(rb[it].z), f2tf(rb[it].w) };
            *(uint4*)&Bs[brow + it * 16][bcol] = v;
        }
        __syncthreads();
        if (kc + 1 < 24) {
            const int k1 = (kc + 1) * 32;
#pragma unroll
            for (int it = 0; it < 4; it++)
                ra[it] = *(const float4*)&X[(m0 + arow + it * 32) * DD + k1 + acol];
#pragma unroll
            for (int it = 0; it < 2; it++)
                rb[it] = *(const float4*)&W[(k1 + brow + it * 16) * DD + n0 + bcol];
        }
#pragma unroll
        for (int kk = 0; kk < 4; kk++) {
            unsigned afr[2][4], bfr[4][2];
#pragma unroll
            for (int ms = 0; ms < 2; ms++) {
                const int r = wm * 32 + ms * 16 + gid;
                afr[ms][0] = As[r][kk * 8 + tig];
                afr[ms][1] = As[r + 8][kk * 8 + tig];
                afr[ms][2] = As[r][kk * 8 + tig + 4];
                afr[ms][3] = As[r + 8][kk * 8 + tig + 4];
            }
#pragma unroll
            for (int ns = 0; ns < 4; ns++) {
                const int cc = wn * 32 + ns * 8 + gid;
                bfr[ns][0] = Bs[kk * 8 + tig][cc];
                bfr[ns][1] = Bs[kk * 8 + tig + 4][cc];
            }
#pragma unroll
            for (int ms = 0; ms < 2; ms++)
#pragma unroll
                for (int ns = 0; ns < 4; ns++)
                    mma_tf32(acc[ms][ns], afr[ms], bfr[ns][0], bfr[ns][1]);
        }
        __syncthreads();
    }
#pragma unroll
    for (int ms = 0; ms < 2; ms++) {
        const int r = m0 + wm * 32 + ms * 16 + gid;
#pragma unroll
        for (int ns = 0; ns < 4; ns++) {
            const int c = n0 + wn * 32 + ns * 8 + 2 * tig;
            const float2 bb = *(const float2*)&bias[c];
            float2 v0 = { acc[ms][ns][0] + bb.x, acc[ms][ns][1] + bb.y };
            float2 v1 = { acc[ms][ns][2] + bb.x, acc[ms][ns][3] + bb.y };
            if (round_out) {
                v0.x = __uint_as_float(f2tf(v0.x)); v0.y = __uint_as_float(f2tf(v0.y));
                v1.x = __uint_as_float(f2tf(v1.x)); v1.y = __uint_as_float(f2tf(v1.y));
            }
            *(float2*)&out[r * DD + c]       = v0;
            *(float2*)&out[(r + 8) * DD + c] = v1;
        }
    }
}

// ---------- kernel 2: am[b,h,e] ----------
__global__ void am_kernel(const float* __restrict__ aspect, const float* __restrict__ Wd,
                          const float* __restrict__ bd, const float* __restrict__ Wm)
{
    __shared__ float a_s[BB][DKK];
    const int tid = threadIdx.x;
    if (tid < BB * DKK) {
        const int b = tid / DKK, d = tid % DKK;
        float s = bd[d];
        for (int k = 0; k < DD; k++) s += aspect[b * DD + k] * Wd[k * DKK + d];
        a_s[b][d] = s;
    }
    __syncthreads();
    for (int idx = tid; idx < BB * HH * DKK; idx += 256) {
        const int b = idx / (HH * DKK);
        const int rem = idx % (HH * DKK);
        const int h = rem / DKK, e = rem % DKK;
        float s = 0.f;
#pragma unroll
        for (int d = 0; d < DKK; d++) s += a_s[b][d] * Wm[(h * DKK + d) * DKK + e];
        g_am[idx] = s;
    }
}

// ---------- kernel 3: asc[b,h,t] = tanh(am . k_t + bias_m) ----------
__global__ __launch_bounds__(256) void asc_kernel(const float* __restrict__ bias_m)
{
    const int idx = blockIdx.x * 256 + threadIdx.x;
    const int t = idx % SS, bh = idx / SS;
    const int h = bh % HH, b = bh / HH;
    const float4* amp = (const float4*)&g_am[bh * DKK];
    const float4* kp  = (const float4*)&g_kp[(b * SS + t) * DD + h * DKK];
    float s = 0.f;
#pragma unroll
    for (int i = 0; i < 16; i++) {
        const float4 a = amp[i], k = kp[i];
        s += a.x * k.x + a.y * k.y + a.z * k.z + a.w * k.w;
    }
    g_asc[idx] = tanhf(s + bias_m[0]);
}

// ---------- kernel 4: scores+softmax, single score pass + in-place gmem rescale ----------
// smem floats: q_u 2176 (32x68) | k 17408 (2 x 128x68) | asc 2048 | part 256 | inv 32
#define ATT_SMEM_FLOATS 21920
__global__ __launch_bounds__(256, 2) void attn_kernel(
    const int* __restrict__ mask, const float* __restrict__ short_t, float* __restrict__ out)
{
    extern __shared__ float sm[];
    unsigned* q_u = (unsigned*)sm;           // 32 x 68
    float* k_f    = sm + 2176;               // 2 x 128 x 68
    float* asc_sm = sm + 19584;              // 2048
    float* part   = sm + 21632;              // 32 x 8
    float* inv    = sm + 21888;              // 32

    const int tid = threadIdx.x, lane = tid & 31, wid = tid >> 5;
    const int gid = lane >> 2, tig = lane & 3;
    const int h = blockIdx.y, b = blockIdx.z, s0 = blockIdx.x * 32;

    const float* kbase = &g_kp[b * SS * DD + h * DKK];

    // prologue: cp.async k tile 0
#pragma unroll
    for (int i = 0; i < 8; i++) {
        const int f4 = tid + i * 256;
        const int row = f4 >> 4, c4 = (f4 & 15) * 4;
        cp_async16(&k_f[row * 68 + c4], &kbase[row * DD + c4]);
    }
    CP_COMMIT();

    // q tile (32 rows) -> smem tf32
#pragma unroll
    for (int i = 0; i < 2; i++) {
        const int idx = tid + i * 256;
        const int r = idx >> 4, c = (idx & 15) * 4;
        const float4 qv = *(const float4*)&g_qp[(b * SS + s0 + r) * DD + h * DKK + c];
        uint4 v = { f2tf(qv.x), f2tf(qv.y), f2tf(qv.z), f2tf(qv.w) };
        *(uint4*)&q_u[r * 68 + c] = v;
    }
    {   // asc row
        const float4* src = (const float4*)&g_asc[(b * HH + h) * SS];
        ((float4*)asc_sm)[tid]       = src[tid];
        ((float4*)asc_sm)[tid + 256] = src[tid + 256];
    }
    CP_WAIT0();
    __syncthreads();

    unsigned afr[2][8][4];
#pragma unroll
    for (int mf = 0; mf < 2; mf++)
#pragma unroll
        for (int kk = 0; kk < 8; kk++) {
            const int r = mf * 16 + gid;
            afr[mf][kk][0] = q_u[r * 68 + kk * 8 + tig];
            afr[mf][kk][1] = q_u[(r + 8) * 68 + kk * 8 + tig];
            afr[mf][kk][2] = q_u[r * 68 + kk * 8 + tig + 4];
            afr[mf][kk][3] = q_u[(r + 8) * 68 + kk * 8 + tig + 4];
        }

    float sums[4] = {0.f, 0.f, 0.f, 0.f};
    const int shb = ((b * HH + h) * SS + s0 + gid) * SS;
    const int mkb = (b * SS + s0 + gid) * SS;

    // ---- pass A: 16 iterations, write unnormalized p to out ----
    for (int it = 0; it < 16; it++) {
        const int t0 = it * 128;
        if (it < 15) {
            const int tn = (it + 1) * 128;
            float* kd = k_f + ((it + 1) & 1) * 8704;
#pragma unroll
            for (int i = 0; i < 8; i++) {
                const int f4 = tid + i * 256;
                const int row = f4 >> 4, c4 = (f4 & 15) * 4;
                cp_async16(&kd[row * 68 + c4], &kbase[(tn + row) * DD + c4]);
            }
            CP_COMMIT();
        }
        const unsigned* kb = (const unsigned*)(k_f + (it & 1) * 8704);
#pragma unroll
        for (int ns = 0; ns < 2; ns++) {
            const int nb = wid * 16 + ns * 8;
            float a0c[4] = {0.f, 0.f, 0.f, 0.f};
            float a1c[4] = {0.f, 0.f, 0.f, 0.f};
            const unsigned* kr = kb + (nb + gid) * 68 + tig;
#pragma unroll
            for (int kk = 0; kk < 8; kk++) {
                const unsigned b0 = kr[kk * 8];
                const unsigned b1 = kr[kk * 8 + 4];
                mma_tf32(a0c, afr[0][kk], b0, b1);
                mma_tf32(a1c, afr[1][kk], b0, b1);
            }
            const int c0 = t0 + nb + 2 * tig;
            const float2 av = *(const float2*)&asc_sm[c0];
#pragma unroll
            for (int rr = 0; rr < 4; rr++) {
                const float x0 = (rr < 2) ? a0c[(rr & 1) * 2]     : a1c[(rr & 1) * 2];
                const float x1 = (rr < 2) ? a0c[(rr & 1) * 2 + 1] : a1c[(rr & 1) * 2 + 1];
                const int off = rr * 8 * SS + c0;
                const float2 sh = *(const float2*)&short_t[shb + off];
                const int2  mv = *(const int2*)&mask[mkb + off];
                float sA = x0 * 0.125f + av.x; if (mv.x == 0) sA = -1e9f; sA += sh.x;
                float sB = x1 * 0.125f + av.y; if (mv.y == 0) sB = -1e9f; sB += sh.y;
                const float pA = __expf(sA), pB = __expf(sB);
                sums[rr] += pA + pB;
                *(float2*)&out[shb + off] = make_float2(pA, pB);
            }
        }
        if (it < 15) CP_WAIT0();
        __syncthreads();
    }

    // ---- reduce row sums -> inv ----
#pragma unroll
    for (int rr = 0; rr < 4; rr++) {
        float s = sums[rr];
        s += __shfl_xor_sync(0xffffffff, s, 1);
        s += __shfl_xor_sync(0xffffffff, s, 2);
        if (tig == 0) part[(rr * 8 + gid) * 8 + wid] = s;
    }
    __syncthreads();
    if (tid < 32) {
        float t = 0.f;
#pragma unroll
        for (int w = 0; w < 8; w++) t += part[tid * 8 + w];
        inv[tid] = 1.0f / t;
    }
    __syncthreads();   // also makes all pass-A gmem writes visible CTA-wide

    // ---- pass B: in-place rescale of this CTA's 32 x 2048 out slab ----
    const int ob = ((b * HH + h) * SS + s0) * SS;
#pragma unroll
    for (int i = 0; i < 64; i++) {
        const int idx = tid + i * 256;           // 0..16383 over 32 rows x 512 float4
        const int row = idx >> 9;
        const int c = (idx & 511) * 4;
        const float s = inv[row];
        float4 p = *(const float4*)&out[ob + row * SS + c];
        p.x *= s; p.y *= s; p.z *= s; p.w *= s;
        *(float4*)&out[ob + row * SS + c] = p;
    }
}

extern "C" void kernel_launch(void* const* d_in, const int* in_sizes, int n_in,
                              void* d_out, int out_size) {
    const float* query  = (const float*)d_in[0];
    const float* key    = (const float*)d_in[1];
    const int*   mask   = (const int*)d_in[2];
    const float* short_t= (const float*)d_in[3];
    const float* aspect = (const float*)d_in[4];
    const float* Wq     = (const float*)d_in[5];
    const float* bq     = (const float*)d_in[6];
    const float* Wk     = (const float*)d_in[7];
    const float* bk     = (const float*)d_in[8];
    const float* Wd     = (const float*)d_in[9];
    const float* bd     = (const float*)d_in[10];
    const float* Wm     = (const float*)d_in[11];
    const float* bias_m = (const float*)d_in[12];
    float* out = (float*)d_out;

    static int smem_set = 0;
    if (!smem_set) {
        cudaFuncSetAttribute(attn_kernel, cudaFuncAttributeMaxDynamicSharedMemorySize,
                             ATT_SMEM_FLOATS * 4);
        smem_set = 1;
    }

    proj_kernel<<<dim3(12, 32, 2), 256>>>(query, Wq, bq, key, Wk, bk);
    am_kernel<<<1, 256>>>(aspect, Wd, bd, Wm);
    asc_kernel<<<BB * HH * SS / 256, 256>>>(bias_m);
    attn_kernel<<<dim3(SS / 32, HH, BB), 256, ATT_SMEM_FLOATS * 4>>>(mask, short_t, out);
}

// round 13
// speedup vs baseline: 1.7602x; 1.0534x over previous
#include <cuda_runtime.h>
#include <math.h>

#define BB 2
#define SS 2048
#define DD 768
#define HH 12
#define DKK 64

__device__ float g_qp[BB * SS * DD];
__device__ float g_kp[BB * SS * DD];   // holds tf32-ROUNDED k values
__device__ float g_am[BB * HH * DKK];
__device__ float g_asc[BB * HH * SS];
__device__ unsigned g_mbits[BB * SS * (SS / 32)];   // bit-packed mask, 1 MB

__device__ __forceinline__ unsigned f2tf(float x) {
    unsigned u;
    asm("cvt.rna.tf32.f32 %0, %1;" : "=r"(u) : "f"(x));
    return u;
}

__device__ __forceinline__ void mma_tf32(float c[4], const unsigned a[4],
                                         unsigned b0, unsigned b1) {
    asm volatile(
        "mma.sync.aligned.m16n8k8.row.col.f32.tf32.tf32.f32 "
        "{%0,%1,%2,%3},{%4,%5,%6,%7},{%8,%9},{%0,%1,%2,%3};"
        : "+f"(c[0]), "+f"(c[1]), "+f"(c[2]), "+f"(c[3])
        : "r"(a[0]), "r"(a[1]), "r"(a[2]), "r"(a[3]), "r"(b0), "r"(b1));
}

__device__ __forceinline__ void cp_async16(float* smem_dst, const float* gsrc) {
    unsigned saddr = (unsigned)__cvta_generic_to_shared(smem_dst);
    asm volatile("cp.async.cg.shared.global [%0], [%1], 16;" :: "r"(saddr), "l"(gsrc));
}
#define CP_COMMIT() asm volatile("cp.async.commit_group;")

// ---------- kernel 1: projections C[4096,768] = X @ W + b (z=0:q, z=1:k) ----------
__global__ __launch_bounds__(256) void proj_kernel(
    const float* __restrict__ qin, const float* __restrict__ Wq, const float* __restrict__ bq,
    const float* __restrict__ kin, const float* __restrict__ Wk, const float* __restrict__ bk)
{
    const float *X, *W, *bias; float* out;
    const bool round_out = (blockIdx.z == 1);
    if (!round_out) { X = qin; W = Wq; bias = bq; out = g_qp; }
    else            { X = kin; W = Wk; bias = bk; out = g_kp; }

    __shared__ unsigned As[128][36];
    __shared__ unsigned Bs[32][72];

    const int tid = threadIdx.x, lane = tid & 31, wid = tid >> 5;
    const int gid = lane >> 2, tig = lane & 3;
    const int wm = wid & 3, wn = wid >> 2;
    const int m0 = blockIdx.y * 128, n0 = blockIdx.x * 64;

    float acc[2][4][4];
#pragma unroll
    for (int i = 0; i < 2; i++)
#pragma unroll
        for (int j = 0; j < 4; j++)
#pragma unroll
            for (int k = 0; k < 4; k++) acc[i][j][k] = 0.f;

    const int arow = tid >> 3, acol = (tid & 7) * 4;
    const int brow = tid >> 4, bcol = (tid & 15) * 4;

    float4 ra[4], rb[2];
#pragma unroll
    for (int it = 0; it < 4; it++)
        ra[it] = *(const float4*)&X[(m0 + arow + it * 32) * DD + acol];
#pragma unroll
    for (int it = 0; it < 2; it++)
        rb[it] = *(const float4*)&W[(brow + it * 16) * DD + n0 + bcol];

    for (int kc = 0; kc < 24; kc++) {
#pragma unroll
        for (int it = 0; it < 4; it++) {
            uint4 v = { f2tf(ra[it].x), f2tf(ra[it].y), f2tf(ra[it].z), f2tf(ra[it].w) };
            *(uint4*)&As[arow + it * 32][acol] = v;
        }
#pragma unroll
        for (int it = 0; it < 2; it++) {
            uint4 v = { f2tf(rb[it].x), f2tf(rb[it].y), f2tf(rb[it].z), f2tf(rb[it].w) };
            *(uint4*)&Bs[brow + it * 16][bcol] = v;
        }
        __syncthreads();
        if (kc + 1 < 24) {
            const int k1 = (kc + 1) * 32;
#pragma unroll
            for (int it = 0; it < 4; it++)
                ra[it] = *(const float4*)&X[(m0 + arow + it * 32) * DD + k1 + acol];
#pragma unroll
            for (int it = 0; it < 2; it++)
                rb[it] = *(const float4*)&W[(k1 + brow + it * 16) * DD + n0 + bcol];
        }
#pragma unroll
        for (int kk = 0; kk < 4; kk++) {
            unsigned afr[2][4], bfr[4][2];
#pragma unroll
            for (int ms = 0; ms < 2; ms++) {
                const int r = wm * 32 + ms * 16 + gid;
                afr[ms][0] = As[r][kk * 8 + tig];
                afr[ms][1] = As[r + 8][kk * 8 + tig];
                afr[ms][2] = As[r][kk * 8 + tig + 4];
                afr[ms][3] = As[r + 8][kk * 8 + tig + 4];
            }
#pragma unroll
            for (int ns = 0; ns < 4; ns++) {
                const int cc = wn * 32 + ns * 8 + gid;
                bfr[ns][0] = Bs[kk * 8 + tig][cc];
                bfr[ns][1] = Bs[kk * 8 + tig + 4][cc];
            }
#pragma unroll
            for (int ms = 0; ms < 2; ms++)
#pragma unroll
                for (int ns = 0; ns < 4; ns++)
                    mma_tf32(acc[ms][ns], afr[ms], bfr[ns][0], bfr[ns][1]);
        }
        __syncthreads();
    }
#pragma unroll
    for (int ms = 0; ms < 2; ms++) {
        const int r = m0 + wm * 32 + ms * 16 + gid;
#pragma unroll
        for (int ns = 0; ns < 4; ns++) {
            const int c = n0 + wn * 32 + ns * 8 + 2 * tig;
            const float2 bb = *(const float2*)&bias[c];
            float2 v0 = { acc[ms][ns][0] + bb.x, acc[ms][ns][1] + bb.y };
            float2 v1 = { acc[ms][ns][2] + bb.x, acc[ms][ns][3] + bb.y };
            if (round_out) {
                v0.x = __uint_as_float(f2tf(v0.x)); v0.y = __uint_as_float(f2tf(v0.y));
                v1.x = __uint_as_float(f2tf(v1.x)); v1.y = __uint_as_float(f2tf(v1.y));
            }
            *(float2*)&out[r * DD + c]       = v0;
            *(float2*)&out[(r + 8) * DD + c] = v1;
        }
    }
}

// ---------- kernel 2: am[b,h,e] ----------
__global__ void am_kernel(const float* __restrict__ aspect, const float* __restrict__ Wd,
                          const float* __restrict__ bd, const float* __restrict__ Wm)
{
    __shared__ float a_s[BB][DKK];
    const int tid = threadIdx.x;
    if (tid < BB * DKK) {
        const int b = tid / DKK, d = tid % DKK;
        float s = bd[d];
        for (int k = 0; k < DD; k++) s += aspect[b * DD + k] * Wd[k * DKK + d];
        a_s[b][d] = s;
    }
    __syncthreads();
    for (int idx = tid; idx < BB * HH * DKK; idx += 256) {
        const int b = idx / (HH * DKK);
        const int rem = idx % (HH * DKK);
        const int h = rem / DKK, e = rem % DKK;
        float s = 0.f;
#pragma unroll
        for (int d = 0; d < DKK; d++) s += a_s[b][d] * Wm[(h * DKK + d) * DKK + e];
        g_am[idx] = s;
    }
}

// ---------- kernel 3: asc[b,h,t] = tanh(am . k_t + bias_m) ----------
__global__ __launch_bounds__(256) void asc_kernel(const float* __restrict__ bias_m)
{
    const int idx = blockIdx.x * 256 + threadIdx.x;
    const int t = idx % SS, bh = idx / SS;
    const int h = bh % HH, b = bh / HH;
    const float4* amp = (const float4*)&g_am[bh * DKK];
    const float4* kp  = (const float4*)&g_kp[(b * SS + t) * DD + h * DKK];
    float s = 0.f;
#pragma unroll
    for (int i = 0; i < 16; i++) {
        const float4 a = amp[i], k = kp[i];
        s += a.x * k.x + a.y * k.y + a.z * k.z + a.w * k.w;
    }
    g_asc[idx] = tanhf(s + bias_m[0]);
}

// ---------- kernel 3b: pack mask into bits ----------
__global__ __launch_bounds__(256) void mask_pack_kernel(const int* __restrict__ mask)
{
    const int lane = threadIdx.x & 31, wrp = threadIdx.x >> 5;
    const int row = blockIdx.x * 8 + wrp;            // 0 .. BB*SS-1
    const int* src = mask + (long long)row * SS;
#pragma unroll
    for (int w = 0; w < 64; w++) {
        const int v = src[w * 32 + lane];
        const unsigned bits = __ballot_sync(0xffffffff, v != 0);
        if (lane == 0) g_mbits[row * 64 + w] = bits;
    }
}

// ---------- kernel 4: scores+softmax — free-running warps, per-warp k pipeline ----------
// smem floats: q 2176 | k 8w x 2 x 16x68 = 17408 | asc 2048 | mbits 2048 | part 256 | inv 32
#define ATT_SMEM_FLOATS 23968
__global__ __launch_bounds__(256, 2) void attn_kernel(
    const float* __restrict__ short_t, float* __restrict__ out)
{
    extern __shared__ float sm[];
    unsigned* q_u = (unsigned*)sm;            // 32 x 68
    float* k_f    = sm + 2176;                // per-warp slabs
    float* asc_sm = sm + 19584;               // 2048
    unsigned* mb  = (unsigned*)(sm + 21632);  // 32 x 64
    float* part   = sm + 23680;               // 32 x 8
    float* inv    = sm + 23936;               // 32

    const int tid = threadIdx.x, lane = tid & 31, wid = tid >> 5;
    const int gid = lane >> 2, tig = lane & 3;
    const int h = blockIdx.y, b = blockIdx.z, s0 = blockIdx.x * 32;

    const int nbase = wid * 16;                        // warp's column slice in each tile
    float* kslab = k_f + wid * 2176;                   // 2 x 16 x 68
    const float* kwarp = &g_kp[b * SS * DD + h * DKK] + nbase * DD;

    // per-warp prologue: cp.async own slice of tile 0
#pragma unroll
    for (int i = 0; i < 8; i++) {
        const int f4 = lane + i * 32;
        const int row = f4 >> 4, c4 = (f4 & 15) * 4;
        cp_async16(&kslab[row * 68 + c4], &kwarp[row * DD + c4]);
    }
    CP_COMMIT();

    // q tile (32 rows) -> smem tf32
#pragma unroll
    for (int i = 0; i < 2; i++) {
        const int idx = tid + i * 256;
        const int r = idx >> 4, c = (idx & 15) * 4;
        const float4 qv = *(const float4*)&g_qp[(b * SS + s0 + r) * DD + h * DKK + c];
        uint4 v = { f2tf(qv.x), f2tf(qv.y), f2tf(qv.z), f2tf(qv.w) };
        *(uint4*)&q_u[r * 68 + c] = v;
    }
    {   // asc row
        const float4* src = (const float4*)&g_asc[(b * HH + h) * SS];
        ((float4*)asc_sm)[tid]       = src[tid];
        ((float4*)asc_sm)[tid + 256] = src[tid + 256];
    }
    {   // mask bits for this CTA's 32 rows
#pragma unroll
        for (int i = 0; i < 8; i++) {
            const int idx = tid + i * 256;        // 0..2047
            mb[idx] = g_mbits[(b * SS + s0 + (idx >> 6)) * 64 + (idx & 63)];
        }
    }
    __syncthreads();

    unsigned afr[2][8][4];
#pragma unroll
    for (int mf = 0; mf < 2; mf++)
#pragma unroll
        for (int kk = 0; kk < 8; kk++) {
            const int r = mf * 16 + gid;
            afr[mf][kk][0] = q_u[r * 68 + kk * 8 + tig];
            afr[mf][kk][1] = q_u[(r + 8) * 68 + kk * 8 + tig];
            afr[mf][kk][2] = q_u[r * 68 + kk * 8 + tig + 4];
            afr[mf][kk][3] = q_u[(r + 8) * 68 + kk * 8 + tig + 4];
        }

    float sums[4] = {0.f, 0.f, 0.f, 0.f};
    const int shb = ((b * HH + h) * SS + s0 + gid) * SS;

    // ---- pass A: 16 tiles, NO CTA barriers — per-warp cp.async pipeline ----
    for (int it = 0; it < 16; it++) {
        const int t0 = it * 128;
        if (it < 15) {
            const int tn = (it + 1) * 128;
            float* kd = kslab + ((it + 1) & 1) * 1088;
#pragma unroll
            for (int i = 0; i < 8; i++) {
                const int f4 = lane + i * 32;
                const int row = f4 >> 4, c4 = (f4 & 15) * 4;
                cp_async16(&kd[row * 68 + c4], &kwarp[(tn + row) * DD + c4]);
            }
            CP_COMMIT();
            asm volatile("cp.async.wait_group 1;");
        } else {
            asm volatile("cp.async.wait_group 0;");
        }
        __syncwarp();
        const unsigned* kb = (const unsigned*)(kslab + (it & 1) * 1088);
#pragma unroll
        for (int ns = 0; ns < 2; ns++) {
            float a0c[4] = {0.f, 0.f, 0.f, 0.f};
            float a1c[4] = {0.f, 0.f, 0.f, 0.f};
            const unsigned* kr = kb + (ns * 8 + gid) * 68 + tig;
#pragma unroll
            for (int kk = 0; kk < 8; kk++) {
                const unsigned b0 = kr[kk * 8];
                const unsigned b1 = kr[kk * 8 + 4];
                mma_tf32(a0c, afr[0][kk], b0, b1);
                mma_tf32(a1c, afr[1][kk], b0, b1);
            }
            const int c0 = t0 + nbase + ns * 8 + 2 * tig;
            const float2 av = *(const float2*)&asc_sm[c0];
#pragma unroll
            for (int rr = 0; rr < 4; rr++) {
                const float x0 = (rr < 2) ? a0c[(rr & 1) * 2]     : a1c[(rr & 1) * 2];
                const float x1 = (rr < 2) ? a0c[(rr & 1) * 2 + 1] : a1c[(rr & 1) * 2 + 1];
                const int off = rr * 8 * SS + c0;
                const float2 sh = *(const float2*)&short_t[shb + off];
                const unsigned mw = mb[(rr * 8 + gid) * 64 + (c0 >> 5)];
                float sA = x0 * 0.125f + av.x;
                if (!((mw >> (c0 & 31)) & 1u)) sA = -1e9f;
                sA += sh.x;
                float sB = x1 * 0.125f + av.y;
                if (!((mw >> ((c0 + 1) & 31)) & 1u)) sB = -1e9f;
                sB += sh.y;
                const float pA = __expf(sA), pB = __expf(sB);
                sums[rr] += pA + pB;
                *(float2*)&out[shb + off] = make_float2(pA, pB);
            }
        }
        __syncwarp();   // protect kslab buffer reuse across the warp
    }

    // ---- reduce row sums -> inv ----
#pragma unroll
    for (int rr = 0; rr < 4; rr++) {
        float s = sums[rr];
        s += __shfl_xor_sync(0xffffffff, s, 1);
        s += __shfl_xor_sync(0xffffffff, s, 2);
        if (tig == 0) part[(rr * 8 + gid) * 8 + wid] = s;
    }
    __syncthreads();
    if (tid < 32) {
        float t = 0.f;
#pragma unroll
        for (int w = 0; w < 8; w++) t += part[tid * 8 + w];
        inv[tid] = 1.0f / t;
    }
    __syncthreads();   // pass-A gmem writes of all warps now visible

    // ---- pass B: in-place rescale of this CTA's 32 x 2048 out slab ----
    const int ob = ((b * HH + h) * SS + s0) * SS;
#pragma unroll
    for (int i = 0; i < 64; i++) {
        const int idx = tid + i * 256;
        const int row = idx >> 9;
        const int c = (idx & 511) * 4;
        const float s = inv[row];
        float4 p = *(const float4*)&out[ob + row * SS + c];
        p.x *= s; p.y *= s; p.z *= s; p.w *= s;
        *(float4*)&out[ob + row * SS + c] = p;
    }
}

extern "C" void kernel_launch(void* const* d_in, const int* in_sizes, int n_in,
                              void* d_out, int out_size) {
    const float* query  = (const float*)d_in[0];
    const float* key    = (const float*)d_in[1];
    const int*   mask   = (const int*)d_in[2];
    const float* short_t= (const float*)d_in[3];
    const float* aspect = (const float*)d_in[4];
    const float* Wq     = (const float*)d_in[5];
    const float* bq     = (const float*)d_in[6];
    const float* Wk     = (const float*)d_in[7];
    const float* bk     = (const float*)d_in[8];
    const float* Wd     = (const float*)d_in[9];
    const float* bd     = (const float*)d_in[10];
    const float* Wm     = (const float*)d_in[11];
    const float* bias_m = (const float*)d_in[12];
    float* out = (float*)d_out;

    static int smem_set = 0;
    if (!smem_set) {
        cudaFuncSetAttribute(attn_kernel, cudaFuncAttributeMaxDynamicSharedMemorySize,
                             ATT_SMEM_FLOATS * 4);
        smem_set = 1;
    }

    proj_kernel<<<dim3(12, 32, 2), 256>>>(query, Wq, bq, key, Wk, bk);
    mask_pack_kernel<<<BB * SS / 8, 256>>>(mask);
    am_kernel<<<1, 256>>>(aspect, Wd, bd, Wm);
    asc_kernel<<<BB * HH * SS / 256, 256>>>(bias_m);
    attn_kernel<<<dim3(SS / 32, HH, BB), 256, ATT_SMEM_FLOATS * 4>>>(short_t, out);
}

// round 15
// speedup vs baseline: 1.7997x; 1.0225x over previous
#include <cuda_runtime.h>
#include <cuda_fp16.h>
#include <math.h>

#define BB 2
#define SS 2048
#define DD 768
#define HH 12
#define DKK 64

__device__ float g_qp[BB * SS * DD];
__device__ float g_kp[BB * SS * DD];   // holds tf32-ROUNDED k values
__device__ float g_am[BB * HH * DKK];
__device__ float g_asc[BB * HH * SS];
__device__ unsigned g_mbits[BB * SS * (SS / 32)];   // bit-packed mask, 1 MB
__device__ __half g_ph[BB * HH * SS * SS];          // unnormalized p scratch (fp16)

__device__ __forceinline__ unsigned f2tf(float x) {
    unsigned u;
    asm("cvt.rna.tf32.f32 %0, %1;" : "=r"(u) : "f"(x));
    return u;
}

__device__ __forceinline__ void mma_tf32(float c[4], const unsigned a[4],
                                         unsigned b0, unsigned b1) {
    asm volatile(
        "mma.sync.aligned.m16n8k8.row.col.f32.tf32.tf32.f32 "
        "{%0,%1,%2,%3},{%4,%5,%6,%7},{%8,%9},{%0,%1,%2,%3};"
        : "+f"(c[0]), "+f"(c[1]), "+f"(c[2]), "+f"(c[3])
        : "r"(a[0]), "r"(a[1]), "r"(a[2]), "r"(a[3]), "r"(b0), "r"(b1));
}

__device__ __forceinline__ void cp_async16(float* smem_dst, const float* gsrc) {
    unsigned saddr = (unsigned)__cvta_generic_to_shared(smem_dst);
    asm volatile("cp.async.cg.shared.global [%0], [%1], 16;" :: "r"(saddr), "l"(gsrc));
}
#define CP_COMMIT() asm volatile("cp.async.commit_group;")

// ---------- kernel 1: projections C[4096,768] = X @ W + b (z=0:q, z=1:k) ----------
__global__ __launch_bounds__(256) void proj_kernel(
    const float* __restrict__ qin, const float* __restrict__ Wq, const float* __restrict__ bq,
    const float* __restrict__ kin, const float* __restrict__ Wk, const float* __restrict__ bk)
{
    const float *X, *W, *bias; float* out;
    const bool round_out = (blockIdx.z == 1);
    if (!round_out) { X = qin; W = Wq; bias = bq; out = g_qp; }
    else            { X = kin; W = Wk; bias = bk; out = g_kp; }

    __shared__ unsigned As[128][36];
    __shared__ unsigned Bs[32][72];

    const int tid = threadIdx.x, lane = tid & 31, wid = tid >> 5;
    const int gid = lane >> 2, tig = lane & 3;
    const int wm = wid & 3, wn = wid >> 2;
    const int m0 = blockIdx.y * 128, n0 = blockIdx.x * 64;

    float acc[2][4][4];
#pragma unroll
    for (int i = 0; i < 2; i++)
#pragma unroll
        for (int j = 0; j < 4; j++)
#pragma unroll
            for (int k = 0; k < 4; k++) acc[i][j][k] = 0.f;

    const int arow = tid >> 3, acol = (tid & 7) * 4;
    const int brow = tid >> 4, bcol = (tid & 15) * 4;

    float4 ra[4], rb[2];
#pragma unroll
    for (int it = 0; it < 4; it++)
        ra[it] = *(const float4*)&X[(m0 + arow + it * 32) * DD + acol];
#pragma unroll
    for (int it = 0; it < 2; it++)
        rb[it] = *(const float4*)&W[(brow + it * 16) * DD + n0 + bcol];

    for (int kc = 0; kc < 24; kc++) {
#pragma unroll
        for (int it = 0; it < 4; it++) {
            uint4 v = { f2tf(ra[it].x), f2tf(ra[it].y), f2tf(ra[it].z), f2tf(ra[it].w) };
            *(uint4*)&As[arow + it * 32][acol] = v;
        }
#pragma unroll
        for (int it = 0; it < 2; it++) {
            uint4 v = { f2tf(rb[it].x), f2tf(rb[it].y), f2tf(rb[it].z), f2tf(rb[it].w) };
            *(uint4*)&Bs[brow + it * 16][bcol] = v;
        }
        __syncthreads();
        if (kc + 1 < 24) {
            const int k1 = (kc + 1) * 32;
#pragma unroll
            for (int it = 0; it < 4; it++)
                ra[it] = *(const float4*)&X[(m0 + arow + it * 32) * DD + k1 + acol];
#pragma unroll
            for (int it = 0; it < 2; it++)
                rb[it] = *(const float4*)&W[(k1 + brow + it * 16) * DD + n0 + bcol];
        }
#pragma unroll
        for (int kk = 0; kk < 4; kk++) {
            unsigned afr[2][4], bfr[4][2];
#pragma unroll
            for (int ms = 0; ms < 2; ms++) {
                const int r = wm * 32 + ms * 16 + gid;
                afr[ms][0] = As[r][kk * 8 + tig];
                afr[ms][1] = As[r + 8][kk * 8 + tig];
                afr[ms][2] = As[r][kk * 8 + tig + 4];
                afr[ms][3] = As[r + 8][kk * 8 + tig + 4];
            }
#pragma unroll
            for (int ns = 0; ns < 4; ns++) {
                const int cc = wn * 32 + ns * 8 + gid;
                bfr[ns][0] = Bs[kk * 8 + tig][cc];
                bfr[ns][1] = Bs[kk * 8 + tig + 4][cc];
            }
#pragma unroll
            for (int ms = 0; ms < 2; ms++)
#pragma unroll
                for (int ns = 0; ns < 4; ns++)
                    mma_tf32(acc[ms][ns], afr[ms], bfr[ns][0], bfr[ns][1]);
        }
        __syncthreads();
    }
#pragma unroll
    for (int ms = 0; ms < 2; ms++) {
        const int r = m0 + wm * 32 + ms * 16 + gid;
#pragma unroll
        for (int ns = 0; ns < 4; ns++) {
            const int c = n0 + wn * 32 + ns * 8 + 2 * tig;
            const float2 bb = *(const float2*)&bias[c];
            float2 v0 = { acc[ms][ns][0] + bb.x, acc[ms][ns][1] + bb.y };
            float2 v1 = { acc[ms][ns][2] + bb.x, acc[ms][ns][3] + bb.y };
            if (round_out) {
                v0.x = __uint_as_float(f2tf(v0.x)); v0.y = __uint_as_float(f2tf(v0.y));
                v1.x = __uint_as_float(f2tf(v1.x)); v1.y = __uint_as_float(f2tf(v1.y));
            }
            *(float2*)&out[r * DD + c]       = v0;
            *(float2*)&out[(r + 8) * DD + c] = v1;
        }
    }
}

// ---------- kernel 2: am[b,h,e] ----------
__global__ void am_kernel(const float* __restrict__ aspect, const float* __restrict__ Wd,
                          const float* __restrict__ bd, const float* __restrict__ Wm)
{
    __shared__ float a_s[BB][DKK];
    const int tid = threadIdx.x;
    if (tid < BB * DKK) {
        const int b = tid / DKK, d = tid % DKK;
        float s = bd[d];
        for (int k = 0; k < DD; k++) s += aspect[b * DD + k] * Wd[k * DKK + d];
        a_s[b][d] = s;
    }
    __syncthreads();
    for (int idx = tid; idx < BB * HH * DKK; idx += 256) {
        const int b = idx / (HH * DKK);
        const int rem = idx % (HH * DKK);
        const int h = rem / DKK, e = rem % DKK;
        float s = 0.f;
#pragma unroll
        for (int d = 0; d < DKK; d++) s += a_s[b][d] * Wm[(h * DKK + d) * DKK + e];
        g_am[idx] = s;
    }
}

// ---------- kernel 3: asc[b,h,t] = tanh(am . k_t + bias_m) ----------
__global__ __launch_bounds__(256) void asc_kernel(const float* __restrict__ bias_m)
{
    const int idx = blockIdx.x * 256 + threadIdx.x;
    const int t = idx % SS, bh = idx / SS;
    const int h = bh % HH, b = bh / HH;
    const float4* amp = (const float4*)&g_am[bh * DKK];
    const float4* kp  = (const float4*)&g_kp[(b * SS + t) * DD + h * DKK];
    float s = 0.f;
#pragma unroll
    for (int i = 0; i < 16; i++) {
        const float4 a = amp[i], k = kp[i];
        s += a.x * k.x + a.y * k.y + a.z * k.z + a.w * k.w;
    }
    g_asc[idx] = tanhf(s + bias_m[0]);
}

// ---------- kernel 3b: pack mask into bits ----------
__global__ __launch_bounds__(256) void mask_pack_kernel(const int* __restrict__ mask)
{
    const int lane = threadIdx.x & 31, wrp = threadIdx.x >> 5;
    const int row = blockIdx.x * 8 + wrp;            // 0 .. BB*SS-1
    const int* src = mask + (long long)row * SS;
#pragma unroll
    for (int w = 0; w < 64; w++) {
        const int v = src[w * 32 + lane];
        const unsigned bits = __ballot_sync(0xffffffff, v != 0);
        if (lane == 0) g_mbits[row * 64 + w] = bits;
    }
}

// ---------- kernel 4: scores+softmax — free-running warps, fp16 p scratch ----------
// smem floats: q 2176 | k 8w x 2 x 16x68 = 17408 | asc 2048 | mbits 2048 | part 256 | inv 32
#define ATT_SMEM_FLOATS 23968
__global__ __launch_bounds__(256, 2) void attn_kernel(
    const float* __restrict__ short_t, float* __restrict__ out)
{
    extern __shared__ float sm[];
    unsigned* q_u = (unsigned*)sm;            // 32 x 68
    float* k_f    = sm + 2176;                // per-warp slabs
    float* asc_sm = sm + 19584;               // 2048
    unsigned* mb  = (unsigned*)(sm + 21632);  // 32 x 64
    float* part   = sm + 23680;               // 32 x 8
    float* inv    = sm + 23936;               // 32

    const int tid = threadIdx.x, lane = tid & 31, wid = tid >> 5;
    const int gid = lane >> 2, tig = lane & 3;
    const int h = blockIdx.y, b = blockIdx.z, s0 = blockIdx.x * 32;

    const int nbase = wid * 16;                        // warp's column slice in each tile
    float* kslab = k_f + wid * 2176;                   // 2 x 16 x 68
    const float* kwarp = &g_kp[b * SS * DD + h * DKK] + nbase * DD;

    // per-warp prologue: cp.async own slice of tile 0
#pragma unroll
    for (int i = 0; i < 8; i++) {
        const int f4 = lane + i * 32;
        const int row = f4 >> 4, c4 = (f4 & 15) * 4;
        cp_async16(&kslab[row * 68 + c4], &kwarp[row * DD + c4]);
    }
    CP_COMMIT();

    // q tile (32 rows) -> smem tf32
#pragma unroll
    for (int i = 0; i < 2; i++) {
        const int idx = tid + i * 256;
        const int r = idx >> 4, c = (idx & 15) * 4;
        const float4 qv = *(const float4*)&g_qp[(b * SS + s0 + r) * DD + h * DKK + c];
        uint4 v = { f2tf(qv.x), f2tf(qv.y), f2tf(qv.z), f2tf(qv.w) };
        *(uint4*)&q_u[r * 68 + c] = v;
    }
    {   // asc row
        const float4* src = (const float4*)&g_asc[(b * HH + h) * SS];
        ((float4*)asc_sm)[tid]       = src[tid];
        ((float4*)asc_sm)[tid + 256] = src[tid + 256];
    }
    {   // mask bits for this CTA's 32 rows
#pragma unroll
        for (int i = 0; i < 8; i++) {
            const int idx = tid + i * 256;        // 0..2047
            mb[idx] = g_mbits[(b * SS + s0 + (idx >> 6)) * 64 + (idx & 63)];
        }
    }
    __syncthreads();

    unsigned afr[2][8][4];
#pragma unroll
    for (int mf = 0; mf < 2; mf++)
#pragma unroll
        for (int kk = 0; kk < 8; kk++) {
            const int r = mf * 16 + gid;
            afr[mf][kk][0] = q_u[r * 68 + kk * 8 + tig];
            afr[mf][kk][1] = q_u[(r + 8) * 68 + kk * 8 + tig];
            afr[mf][kk][2] = q_u[r * 68 + kk * 8 + tig + 4];
            afr[mf][kk][3] = q_u[(r + 8) * 68 + kk * 8 + tig + 4];
        }

    float sums[4] = {0.f, 0.f, 0.f, 0.f};
    const int shb = ((b * HH + h) * SS + s0 + gid) * SS;

    // ---- pass A: 16 tiles, NO CTA barriers — per-warp cp.async pipeline ----
    for (int it = 0; it < 16; it++) {
        const int t0 = it * 128;
        if (it < 15) {
            const int tn = (it + 1) * 128;
            float* kd = kslab + ((it + 1) & 1) * 1088;
#pragma unroll
            for (int i = 0; i < 8; i++) {
                const int f4 = lane + i * 32;
                const int row = f4 >> 4, c4 = (f4 & 15) * 4;
                cp_async16(&kd[row * 68 + c4], &kwarp[(tn + row) * DD + c4]);
            }
            CP_COMMIT();
            asm volatile("cp.async.wait_group 1;");
        } else {
            asm volatile("cp.async.wait_group 0;");
        }
        __syncwarp();
        const unsigned* kb = (const unsigned*)(kslab + (it & 1) * 1088);
#pragma unroll
        for (int ns = 0; ns < 2; ns++) {
            float a0c[4] = {0.f, 0.f, 0.f, 0.f};
            float a1c[4] = {0.f, 0.f, 0.f, 0.f};
            const unsigned* kr = kb + (ns * 8 + gid) * 68 + tig;
#pragma unroll
            for (int kk = 0; kk < 8; kk++) {
                const unsigned b0 = kr[kk * 8];
                const unsigned b1 = kr[kk * 8 + 4];
                mma_tf32(a0c, afr[0][kk], b0, b1);
                mma_tf32(a1c, afr[1][kk], b0, b1);
            }
            const int c0 = t0 + nbase + ns * 8 + 2 * tig;
            const float2 av = *(const float2*)&asc_sm[c0];
#pragma unroll
            for (int rr = 0; rr < 4; rr++) {
                const float x0 = (rr < 2) ? a0c[(rr & 1) * 2]     : a1c[(rr & 1) * 2];
                const float x1 = (rr < 2) ? a0c[(rr & 1) * 2 + 1] : a1c[(rr & 1) * 2 + 1];
                const int off = rr * 8 * SS + c0;
                const float2 sh = *(const float2*)&short_t[shb + off];
                const unsigned mw = mb[(rr * 8 + gid) * 64 + (c0 >> 5)];
                float sA = x0 * 0.125f + av.x;
                if (!((mw >> (c0 & 31)) & 1u)) sA = -1e9f;
                sA += sh.x;
                float sB = x1 * 0.125f + av.y;
                if (!((mw >> ((c0 + 1) & 31)) & 1u)) sB = -1e9f;
                sB += sh.y;
                const float pA = __expf(sA), pB = __expf(sB);
                sums[rr] += pA + pB;
                *(__half2*)&g_ph[shb + off] = __floats2half2_rn(pA, pB);
            }
        }
        __syncwarp();   // protect kslab buffer reuse across the warp
    }

    // ---- reduce row sums -> inv ----
#pragma unroll
    for (int rr = 0; rr < 4; rr++) {
        float s = sums[rr];
        s += __shfl_xor_sync(0xffffffff, s, 1);
        s += __shfl_xor_sync(0xffffffff, s, 2);
        if (tig == 0) part[(rr * 8 + gid) * 8 + wid] = s;
    }
    __syncthreads();
    if (tid < 32) {
        float t = 0.f;
#pragma unroll
        for (int w = 0; w < 8; w++) t += part[tid * 8 + w];
        inv[tid] = 1.0f / t;
    }
    __syncthreads();   // pass-A gmem writes of all warps now visible

    // ---- pass B: g_ph (fp16) -> normalized fp32 out, single coalesced write ----
    const int ob = ((b * HH + h) * SS + s0) * SS;
#pragma unroll
    for (int i = 0; i < 64; i++) {
        const int idx = tid + i * 256;           // 0..16383 float4 over 32 rows
        const int row = idx >> 9;
        const int c = (idx & 511) * 4;
        const float s = inv[row];
        const uint2 u = *(const uint2*)&g_ph[ob + row * SS + c];
        const float2 f0 = __half22float2(*(const __half2*)&u.x);
        const float2 f1 = __half22float2(*(const __half2*)&u.y);
        float4 p = { f0.x * s, f0.y * s, f1.x * s, f1.y * s };
        *(float4*)&out[ob + row * SS + c] = p;
    }
}

extern "C" void kernel_launch(void* const* d_in, const int* in_sizes, int n_in,
                              void* d_out, int out_size) {
    const float* query  = (const float*)d_in[0];
    const float* key    = (const float*)d_in[1];
    const int*   mask   = (const int*)d_in[2];
    const float* short_t= (const float*)d_in[3];
    const float* aspect = (const float*)d_in[4];
    const float* Wq     = (const float*)d_in[5];
    const float* bq     = (const float*)d_in[6];
    const float* Wk     = (const float*)d_in[7];
    const float* bk     = (const float*)d_in[8];
    const float* Wd     = (const float*)d_in[9];
    const float* bd     = (const float*)d_in[10];
    const float* Wm     = (const float*)d_in[11];
    const float* bias_m = (const float*)d_in[12];
    float* out = (float*)d_out;

    static int smem_set = 0;
    if (!smem_set) {
        cudaFuncSetAttribute(attn_kernel, cudaFuncAttributeMaxDynamicSharedMemorySize,
                             ATT_SMEM_FLOATS * 4);
        smem_set = 1;
    }

    proj_kernel<<<dim3(12, 32, 2), 256>>>(query, Wq, bq, key, Wk, bk);
    mask_pack_kernel<<<BB * SS / 8, 256>>>(mask);
    am_kernel<<<1, 256>>>(aspect, Wd, bd, Wm);
    asc_kernel<<<BB * HH * SS / 256, 256>>>(bias_m);
    attn_kernel<<<dim3(SS / 32, HH, BB), 256, ATT_SMEM_FLOATS * 4>>>(short_t, out);
}

// round 17
// speedup vs baseline: 2.1380x; 1.1880x over previous
#include <cuda_runtime.h>
#include <cuda_fp16.h>
#include <math.h>

#define BB 2
#define SS 2048
#define DD 768
#define HH 12
#define DKK 64

__device__ float g_qp[BB * SS * DD];
__device__ float g_kp[BB * SS * DD];   // holds tf32-ROUNDED k values
__device__ float g_am[BB * HH * DKK];
__device__ float g_asc[BB * HH * SS];
__device__ unsigned g_mbits[BB * SS * (SS / 32)];   // bit-packed mask, 1 MB
__device__ __half g_ph[BB * HH * SS * SS];          // unnormalized p scratch (fp16)
__device__ float g_inv[BB * HH * SS];               // per-row 1/sum
// tf32-pre-rounded copies of proj inputs
__device__ float g_xq[BB * SS * DD];
__device__ float g_xk[BB * SS * DD];
__device__ float g_wq[DD * DD];
__device__ float g_wk[DD * DD];

__device__ __forceinline__ unsigned f2tf(float x) {
    unsigned u;
    asm("cvt.rna.tf32.f32 %0, %1;" : "=r"(u) : "f"(x));
    return u;
}

__device__ __forceinline__ void mma_tf32(float c[4], const unsigned a[4],
                                         unsigned b0, unsigned b1) {
    asm volatile(
        "mma.sync.aligned.m16n8k8.row.col.f32.tf32.tf32.f32 "
        "{%0,%1,%2,%3},{%4,%5,%6,%7},{%8,%9},{%0,%1,%2,%3};"
        : "+f"(c[0]), "+f"(c[1]), "+f"(c[2]), "+f"(c[3])
        : "r"(a[0]), "r"(a[1]), "r"(a[2]), "r"(a[3]), "r"(b0), "r"(b1));
}

__device__ __forceinline__ void cp_async16(float* smem_dst, const float* gsrc) {
    unsigned saddr = (unsigned)__cvta_generic_to_shared(smem_dst);
    asm volatile("cp.async.cg.shared.global [%0], [%1], 16;" :: "r"(saddr), "l"(gsrc));
}
#define CP_COMMIT() asm volatile("cp.async.commit_group;")

// ---------- kernel 0: elementwise tf32 pre-round ----------
__global__ __launch_bounds__(256) void round_kernel(const float* __restrict__ in,
                                                    float* __restrict__ out, int n4)
{
    const int i = blockIdx.x * 256 + threadIdx.x;
    if (i < n4) {
        const float4 v = ((const float4*)in)[i];
        float4 r;
        r.x = __uint_as_float(f2tf(v.x));
        r.y = __uint_as_float(f2tf(v.y));
        r.z = __uint_as_float(f2tf(v.z));
        r.w = __uint_as_float(f2tf(v.w));
        ((float4*)out)[i] = r;
    }
}

// ---------- kernel 1: projections C[4096,768] = X @ W + b (z=0:q, z=1:k) ----------
// inputs are PRE-ROUNDED tf32 floats; cp.async double-buffered chunks.
// dyn smem floats: As 2 x 128x36 = 9216 | Bs 2 x 32x72 = 4608  -> 13824
#define PROJ_SMEM_FLOATS 13824
__global__ __launch_bounds__(256) void proj_kernel(
    const float* __restrict__ bq, const float* __restrict__ bk)
{
    extern __shared__ float psm[];
    const bool round_out = (blockIdx.z == 1);
    const float* X = round_out ? g_xk : g_xq;
    const float* W = round_out ? g_wk : g_wq;
    const float* bias = round_out ? bk : bq;
    float* out = round_out ? g_kp : g_qp;

    float* As = psm;            // 2 x 128 x 36
    float* Bs = psm + 9216;     // 2 x 32 x 72

    const int tid = threadIdx.x, lane = tid & 31, wid = tid >> 5;
    const int gid = lane >> 2, tig = lane & 3;
    const int wm = wid & 3, wn = wid >> 2;
    const int m0 = blockIdx.y * 128, n0 = blockIdx.x * 64;

    float acc[2][4][4];
#pragma unroll
    for (int i = 0; i < 2; i++)
#pragma unroll
        for (int j = 0; j < 4; j++)
#pragma unroll
            for (int k = 0; k < 4; k++) acc[i][j][k] = 0.f;

    // chunk loader (kc = chunk index, buf = 0/1)
    // A: 128x32 = 1024 float4, B: 32x64 = 512 float4
#define PROJ_LOAD(kc, buf)                                                        \
    {                                                                             \
        float* ad = As + (buf) * 4608;                                            \
        float* bd = Bs + (buf) * 2304;                                            \
        _Pragma("unroll")                                                         \
        for (int i = 0; i < 4; i++) {                                             \
            const int f4 = tid + i * 256;                                         \
            const int ar = f4 >> 3, ac = (f4 & 7) * 4;                            \
            cp_async16(&ad[ar * 36 + ac], &X[(m0 + ar) * DD + (kc) * 32 + ac]);   \
        }                                                                         \
        _Pragma("unroll")                                                         \
        for (int i = 0; i < 2; i++) {                                             \
            const int f4 = tid + i * 256;                                         \
            const int br = f4 >> 4, bc = (f4 & 15) * 4;                           \
            cp_async16(&bd[br * 72 + bc], &W[((kc) * 32 + br) * DD + n0 + bc]);   \
        }                                                                         \
        CP_COMMIT();                                                              \
    }

    PROJ_LOAD(0, 0);

    for (int kc = 0; kc < 24; kc++) {
        if (kc + 1 < 24) {
            PROJ_LOAD(kc + 1, (kc + 1) & 1);
            asm volatile("cp.async.wait_group 1;");
        } else {
            asm volatile("cp.async.wait_group 0;");
        }
        __syncthreads();
        const unsigned* Au = (const unsigned*)(As + (kc & 1) * 4608);
        const unsigned* Bu = (const unsigned*)(Bs + (kc & 1) * 2304);
#pragma unroll
        for (int kk = 0; kk < 4; kk++) {
            unsigned afr[2][4], bfr[4][2];
#pragma unroll
            for (int ms = 0; ms < 2; ms++) {
                const int r = wm * 32 + ms * 16 + gid;
                afr[ms][0] = Au[r * 36 + kk * 8 + tig];
                afr[ms][1] = Au[(r + 8) * 36 + kk * 8 + tig];
                afr[ms][2] = Au[r * 36 + kk * 8 + tig + 4];
                afr[ms][3] = Au[(r + 8) * 36 + kk * 8 + tig + 4];
            }
#pragma unroll
            for (int ns = 0; ns < 4; ns++) {
                const int cc = wn * 32 + ns * 8 + gid;
                bfr[ns][0] = Bu[(kk * 8 + tig) * 72 + cc];
                bfr[ns][1] = Bu[(kk * 8 + tig + 4) * 72 + cc];
            }
#pragma unroll
            for (int ms = 0; ms < 2; ms++)
#pragma unroll
                for (int ns = 0; ns < 4; ns++)
                    mma_tf32(acc[ms][ns], afr[ms], bfr[ns][0], bfr[ns][1]);
        }
        __syncthreads();
    }
#pragma unroll
    for (int ms = 0; ms < 2; ms++) {
        const int r = m0 + wm * 32 + ms * 16 + gid;
#pragma unroll
        for (int ns = 0; ns < 4; ns++) {
            const int c = n0 + wn * 32 + ns * 8 + 2 * tig;
            const float2 bb = *(const float2*)&bias[c];
            float2 v0 = { acc[ms][ns][0] + bb.x, acc[ms][ns][1] + bb.y };
            float2 v1 = { acc[ms][ns][2] + bb.x, acc[ms][ns][3] + bb.y };
            if (round_out) {
                v0.x = __uint_as_float(f2tf(v0.x)); v0.y = __uint_as_float(f2tf(v0.y));
                v1.x = __uint_as_float(f2tf(v1.x)); v1.y = __uint_as_float(f2tf(v1.y));
            }
            *(float2*)&out[r * DD + c]       = v0;
            *(float2*)&out[(r + 8) * DD + c] = v1;
        }
    }
}

// ---------- kernel 2: am[b,h,e] ----------
__global__ void am_kernel(const float* __restrict__ aspect, const float* __restrict__ Wd,
                          const float* __restrict__ bd, const float* __restrict__ Wm)
{
    __shared__ float a_s[BB][DKK];
    const int tid = threadIdx.x;
    if (tid < BB * DKK) {
        const int b = tid / DKK, d = tid % DKK;
        float s = bd[d];
        for (int k = 0; k < DD; k++) s += aspect[b * DD + k] * Wd[k * DKK + d];
        a_s[b][d] = s;
    }
    __syncthreads();
    for (int idx = tid; idx < BB * HH * DKK; idx += 256) {
        const int b = idx / (HH * DKK);
        const int rem = idx % (HH * DKK);
        const int h = rem / DKK, e = rem % DKK;
        float s = 0.f;
#pragma unroll
        for (int d = 0; d < DKK; d++) s += a_s[b][d] * Wm[(h * DKK + d) * DKK + e];
        g_am[idx] = s;
    }
}

// ---------- kernel 3: asc[b,h,t] = tanh(am . k_t + bias_m) ----------
__global__ __launch_bounds__(256) void asc_kernel(const float* __restrict__ bias_m)
{
    const int idx = blockIdx.x * 256 + threadIdx.x;
    const int t = idx % SS, bh = idx / SS;
    const int h = bh % HH, b = bh / HH;
    const float4* amp = (const float4*)&g_am[bh * DKK];
    const float4* kp  = (const float4*)&g_kp[(b * SS + t) * DD + h * DKK];
    float s = 0.f;
#pragma unroll
    for (int i = 0; i < 16; i++) {
        const float4 a = amp[i], k = kp[i];
        s += a.x * k.x + a.y * k.y + a.z * k.z + a.w * k.w;
    }
    g_asc[idx] = tanhf(s + bias_m[0]);
}

// ---------- kernel 3b: pack mask into bits ----------
__global__ __launch_bounds__(256) void mask_pack_kernel(const int* __restrict__ mask)
{
    const int lane = threadIdx.x & 31, wrp = threadIdx.x >> 5;
    const int row = blockIdx.x * 8 + wrp;            // 0 .. BB*SS-1
    const int* src = mask + (long long)row * SS;
#pragma unroll
    for (int w = 0; w < 64; w++) {
        const int v = src[w * 32 + lane];
        const unsigned bits = __ballot_sync(0xffffffff, v != 0);
        if (lane == 0) g_mbits[row * 64 + w] = bits;
    }
}

// ---------- kernel 4: scores pass only — free-running warps, fp16 p + inv out ----------
// smem floats: q 2176 | k 8w x 2 x 16x68 = 17408 | asc 2048 | mbits 2048 | part 256
#define ATT_SMEM_FLOATS 23936
__global__ __launch_bounds__(256, 2) void attn_kernel(
    const float* __restrict__ short_t)
{
    extern __shared__ float sm[];
    unsigned* q_u = (unsigned*)sm;            // 32 x 68
    float* k_f    = sm + 2176;                // per-warp slabs
    float* asc_sm = sm + 19584;               // 2048
    unsigned* mb  = (unsigned*)(sm + 21632);  // 32 x 64
    float* part   = sm + 23680;               // 32 x 8

    const int tid = threadIdx.x, lane = tid & 31, wid = tid >> 5;
    const int gid = lane >> 2, tig = lane & 3;
    const int h = blockIdx.y, b = blockIdx.z, s0 = blockIdx.x * 32;

    const int nbase = wid * 16;
    float* kslab = k_f + wid * 2176;                   // 2 x 16 x 68
    const float* kwarp = &g_kp[b * SS * DD + h * DKK] + nbase * DD;

#pragma unroll
    for (int i = 0; i < 8; i++) {
        const int f4 = lane + i * 32;
        const int row = f4 >> 4, c4 = (f4 & 15) * 4;
        cp_async16(&kslab[row * 68 + c4], &kwarp[row * DD + c4]);
    }
    CP_COMMIT();

#pragma unroll
    for (int i = 0; i < 2; i++) {
        const int idx = tid + i * 256;
        const int r = idx >> 4, c = (idx & 15) * 4;
        const float4 qv = *(const float4*)&g_qp[(b * SS + s0 + r) * DD + h * DKK + c];
        uint4 v = { f2tf(qv.x), f2tf(qv.y), f2tf(qv.z), f2tf(qv.w) };
        *(uint4*)&q_u[r * 68 + c] = v;
    }
    {
        const float4* src = (const float4*)&g_asc[(b * HH + h) * SS];
        ((float4*)asc_sm)[tid]       = src[tid];
        ((float4*)asc_sm)[tid + 256] = src[tid + 256];
    }
#pragma unroll
    for (int i = 0; i < 8; i++) {
        const int idx = tid + i * 256;
        mb[idx] = g_mbits[(b * SS + s0 + (idx >> 6)) * 64 + (idx & 63)];
    }
    __syncthreads();

    unsigned afr[2][8][4];
#pragma unroll
    for (int mf = 0; mf < 2; mf++)
#pragma unroll
        for (int kk = 0; kk < 8; kk++) {
            const int r = mf * 16 + gid;
            afr[mf][kk][0] = q_u[r * 68 + kk * 8 + tig];
            afr[mf][kk][1] = q_u[(r + 8) * 68 + kk * 8 + tig];
            afr[mf][kk][2] = q_u[r * 68 + kk * 8 + tig + 4];
            afr[mf][kk][3] = q_u[(r + 8) * 68 + kk * 8 + tig + 4];
        }

    float sums[4] = {0.f, 0.f, 0.f, 0.f};
    const int shb = ((b * HH + h) * SS + s0 + gid) * SS;

    for (int it = 0; it < 16; it++) {
        const int t0 = it * 128;
        if (it < 15) {
            const int tn = (it + 1) * 128;
            float* kd = kslab + ((it + 1) & 1) * 1088;
#pragma unroll
            for (int i = 0; i < 8; i++) {
                const int f4 = lane + i * 32;
                const int row = f4 >> 4, c4 = (f4 & 15) * 4;
                cp_async16(&kd[row * 68 + c4], &kwarp[(tn + row) * DD + c4]);
            }
            CP_COMMIT();
            asm volatile("cp.async.wait_group 1;");
        } else {
            asm volatile("cp.async.wait_group 0;");
        }
        __syncwarp();
        const unsigned* kb = (const unsigned*)(kslab + (it & 1) * 1088);
#pragma unroll
        for (int ns = 0; ns < 2; ns++) {
            float a0c[4] = {0.f, 0.f, 0.f, 0.f};
            float a1c[4] = {0.f, 0.f, 0.f, 0.f};
            const unsigned* kr = kb + (ns * 8 + gid) * 68 + tig;
#pragma unroll
            for (int kk = 0; kk < 8; kk++) {
                const unsigned b0 = kr[kk * 8];
                const unsigned b1 = kr[kk * 8 + 4];
                mma_tf32(a0c, afr[0][kk], b0, b1);
                mma_tf32(a1c, afr[1][kk], b0, b1);
            }
            const int c0 = t0 + nbase + ns * 8 + 2 * tig;
            const float2 av = *(const float2*)&asc_sm[c0];
#pragma unroll
            for (int rr = 0; rr < 4; rr++) {
                const float x0 = (rr < 2) ? a0c[(rr & 1) * 2]     : a1c[(rr & 1) * 2];
                const float x1 = (rr < 2) ? a0c[(rr & 1) * 2 + 1] : a1c[(rr & 1) * 2 + 1];
                const int off = rr * 8 * SS + c0;
                const float2 sh = *(const float2*)&short_t[shb + off];
                const unsigned mw = mb[(rr * 8 + gid) * 64 + (c0 >> 5)];
                float sA = x0 * 0.125f + av.x;
                if (!((mw >> (c0 & 31)) & 1u)) sA = -1e9f;
                sA += sh.x;
                float sB = x1 * 0.125f + av.y;
                if (!((mw >> ((c0 + 1) & 31)) & 1u)) sB = -1e9f;
                sB += sh.y;
                const float pA = __expf(sA), pB = __expf(sB);
                sums[rr] += pA + pB;
                *(__half2*)&g_ph[shb + off] = __floats2half2_rn(pA, pB);
            }
        }
        __syncwarp();
    }

    // reduce row sums -> g_inv
#pragma unroll
    for (int rr = 0; rr < 4; rr++) {
        float s = sums[rr];
        s += __shfl_xor_sync(0xffffffff, s, 1);
        s += __shfl_xor_sync(0xffffffff, s, 2);
        if (tig == 0) part[(rr * 8 + gid) * 8 + wid] = s;
    }
    __syncthreads();
    if (tid < 32) {
        float t = 0.f;
#pragma unroll
        for (int w = 0; w < 8; w++) t += part[tid * 8 + w];
        g_inv[(b * HH + h) * SS + s0 + tid] = 1.0f / t;
    }
}

// ---------- kernel 5: normalization — one block per output row ----------
__global__ __launch_bounds__(512) void norm_kernel(float* __restrict__ out)
{
    const int row = blockIdx.x;                 // 0 .. BB*HH*SS-1
    const float s = g_inv[row];
    const long long base = (long long)row * SS;
    const int c = threadIdx.x * 4;
    const uint2 u = *(const uint2*)&g_ph[base + c];
    const float2 f0 = __half22float2(*(const __half2*)&u.x);
    const float2 f1 = __half22float2(*(const __half2*)&u.y);
    float4 p = { f0.x * s, f0.y * s, f1.x * s, f1.y * s };
    *(float4*)&out[base + c] = p;
}

extern "C" void kernel_launch(void* const* d_in, const int* in_sizes, int n_in,
                              void* d_out, int out_size) {
    const float* query  = (const float*)d_in[0];
    const float* key    = (const float*)d_in[1];
    const int*   mask   = (const int*)d_in[2];
    const float* short_t= (const float*)d_in[3];
    const float* aspect = (const float*)d_in[4];
    const float* Wq     = (const float*)d_in[5];
    const float* bq     = (const float*)d_in[6];
    const float* Wk     = (const float*)d_in[7];
    const float* bk     = (const float*)d_in[8];
    const float* Wd     = (const float*)d_in[9];
    const float* bd     = (const float*)d_in[10];
    const float* Wm     = (const float*)d_in[11];
    const float* bias_m = (const float*)d_in[12];
    float* out = (float*)d_out;

    static int smem_set = 0;
    if (!smem_set) {
        cudaFuncSetAttribute(attn_kernel, cudaFuncAttributeMaxDynamicSharedMemorySize,
                             ATT_SMEM_FLOATS * 4);
        cudaFuncSetAttribute(proj_kernel, cudaFuncAttributeMaxDynamicSharedMemorySize,
                             PROJ_SMEM_FLOATS * 4);
        smem_set = 1;
    }

    float* gxq; cudaGetSymbolAddress((void**)&gxq, g_xq);
    float* gxk; cudaGetSymbolAddress((void**)&gxk, g_xk);
    float* gwq; cudaGetSymbolAddress((void**)&gwq, g_wq);
    float* gwk; cudaGetSymbolAddress((void**)&gwk, g_wk);

    const int nX4 = BB * SS * DD / 4, nW4 = DD * DD / 4;
    round_kernel<<<(nX4 + 255) / 256, 256>>>(query, gxq, nX4);
    round_kernel<<<(nX4 + 255) / 256, 256>>>(key,   gxk, nX4);
    round_kernel<<<(nW4 + 255) / 256, 256>>>(Wq,    gwq, nW4);
    round_kernel<<<(nW4 + 255) / 256, 256>>>(Wk,    gwk, nW4);

    proj_kernel<<<dim3(12, 32, 2), 256, PROJ_SMEM_FLOATS * 4>>>(bq, bk);
    mask_pack_kernel<<<BB * SS / 8, 256>>>(mask);
    am_kernel<<<1, 256>>>(aspect, Wd, bd, Wm);
    asc_kernel<<<BB * HH * SS / 256, 256>>>(bias_m);
    attn_kernel<<<dim3(SS / 32, HH, BB), 256, ATT_SMEM_FLOATS * 4>>>(short_t);
    norm_kernel<<<BB * HH * SS, 512>>>(out);
}